// round 10
// baseline (speedup 1.0000x reference)
#include <cuda_runtime.h>
#include <cuda_fp16.h>
#include <math.h>

#define DCH    64
#define FAN    192
#define TILE_E 128
#define MAX_NODES 50176

__device__ float g_message[MAX_NODES * DCH];
__device__ unsigned short g_P1h[MAX_NODES * 128];
__device__ unsigned short g_P2h[MAX_NODES * 128];
__device__ float g_sum[DCH];
__device__ float g_sumsq[DCH];
__device__ unsigned short g_Bh[3 * 128 * 64];
__device__ unsigned short g_Bl[3 * 128 * 64];

// ---------------- edge kernel smem (bytes) ----------------
#define EO_SRC   0
#define EO_TGT   512
#define EO_BF    1024
#define EO_BS    1280
#define EO_AH    1536             // 16384 bytes
#define EO_STAGE 17920            // 128 rows x 68 u32 = 34816 bytes
#define EO_BSTG  17920            // startup overlay (32KB <= 34816)
#define STGU     68
#define EDGE_SMEM_BYTES 52736

// ---------------- node kernel smem ----------------
#define NO_AH    0
#define NO_AL    16384
#define NO_BH    32768
#define NO_BL    49152
#define NODE_SMEM_BYTES 65536

// ---------------- helpers ----------------
__device__ __forceinline__ unsigned smem_u32(const void* p) {
    unsigned a;
    asm("{ .reg .u64 t; cvta.to.shared.u64 t, %1; cvt.u32.u64 %0, t; }" : "=r"(a) : "l"(p));
    return a;
}
__device__ __forceinline__ unsigned pack_f16x2(float lo, float hi) {
    unsigned r;
    asm("cvt.rn.f16x2.f32 %0, %1, %2;" : "=r"(r) : "f"(hi), "f"(lo));
    return r;
}
__device__ __forceinline__ float2 unpack_h2(unsigned u) {
    __half2 h = *reinterpret_cast<__half2*>(&u);
    return __half22float2(h);
}
__device__ __forceinline__ float ex2a(float x) { float r; asm("ex2.approx.f32 %0, %1;" : "=f"(r) : "f"(x)); return r; }
__device__ __forceinline__ float lg2a(float x) { float r; asm("lg2.approx.f32 %0, %1;" : "=f"(r) : "f"(x)); return r; }
__device__ __forceinline__ float rcpa(float x) { float r; asm("rcp.approx.f32 %0, %1;" : "=f"(r) : "f"(x)); return r; }
__device__ __forceinline__ float sigmoid_f(float g) {
    return rcpa(1.0f + ex2a(-1.44269504f * g));
}
__device__ __forceinline__ float softplus_f(float v) {
    float u = ex2a(-1.44269504f * fabsf(v));
    return fmaxf(v, 0.0f) + 0.69314718f * lg2a(1.0f + u);
}

#define LDSM4(R, A) \
    asm volatile("ldmatrix.sync.aligned.m8n8.x4.shared.b16 {%0,%1,%2,%3}, [%4];" \
        : "=r"((R)[0]), "=r"((R)[1]), "=r"((R)[2]), "=r"((R)[3]) : "r"(A))
#define LDSM2(R0, R1, A) \
    asm volatile("ldmatrix.sync.aligned.m8n8.x2.shared.b16 {%0,%1}, [%2];" \
        : "=r"(R0), "=r"(R1) : "r"(A))
#define MMA16816(D, A, B0, B1) \
    asm volatile("mma.sync.aligned.m16n8k16.row.col.f32.f16.f16.f32 " \
        "{%0,%1,%2,%3}, {%4,%5,%6,%7}, {%8,%9}, {%0,%1,%2,%3};" \
        : "+f"((D)[0]), "+f"((D)[1]), "+f"((D)[2]), "+f"((D)[3]) \
        : "r"((A)[0]), "r"((A)[1]), "r"((A)[2]), "r"((A)[3]), "r"(B0), "r"(B1))

// ---------------- prep: all 3 W slices -> fp16 hi/lo ----------------
__global__ void prep_B_kernel(const float* __restrict__ Wf, const float* __restrict__ Ws) {
    int idx = blockIdx.x * 256 + threadIdx.x;   // 24576
    int s = idx >> 13;
    int r = idx & 8191;
    int n = r >> 6;
    int k = r & 63;
    int d = n >> 1;
    const float* w = (n & 1) ? Ws : Wf;
    float v = w[d * FAN + s * 64 + k];
    __half h = __float2half_rn(v);
    __half l = __float2half_rn(v - __half2float(h));
    g_Bh[idx] = __half_as_ushort(h);
    g_Bl[idx] = __half_as_ushort(l);
}

// ---------------- zero ----------------
__global__ void zero_kernel(int total4) {
    int i = blockIdx.x * blockDim.x + threadIdx.x;
    int stride = gridDim.x * blockDim.x;
    float4* m4 = (float4*)g_message;
    for (int j = i; j < total4; j += stride) m4[j] = make_float4(0.f, 0.f, 0.f, 0.f);
    if (i < DCH) { g_sum[i] = 0.0f; g_sumsq[i] = 0.0f; }
}

// ---------------- node projections on tensor cores -> fp16 P ----------------
__global__ __launch_bounds__(256, 2)
void node_mma_kernel(const float* __restrict__ x, int n_nodes, int ntiles)
{
    extern __shared__ char smc[];
    unsigned sb = smem_u32(smc);
    const int tid = threadIdx.x;
    const int wsel = blockIdx.y;
    unsigned short* P = wsel ? g_P2h : g_P1h;

    {
        const uint4* bh = (const uint4*)g_Bh + wsel * 1024;
        const uint4* bl = (const uint4*)g_Bl + wsel * 1024;
        #pragma unroll
        for (int j = 0; j < 4; j++) {
            int idx = tid + j * 256;
            int n = idx >> 3;
            int cj = idx & 7;
            unsigned dst = n * 128 + ((cj * 16) ^ ((n & 7) << 4));
            *(uint4*)(smc + NO_BH + dst) = bh[idx];
            *(uint4*)(smc + NO_BL + dst) = bl[idx];
        }
    }

    const int w = tid >> 5;
    const int lane = tid & 31;
    const int m0 = (w & 3) * 32;
    const int nn0 = (w >> 2) * 64;
    const int rA0 = m0 + (lane & 15);
    const unsigned hiA = ((lane >> 4) & 1) << 4;
    const unsigned swA = (rA0 & 7) << 4;
    const int rB = nn0 + (lane & 7);
    const unsigned hiB = ((lane >> 3) & 1) << 4;
    const unsigned swB = (lane & 7) << 4;
    const unsigned boff = sb + NO_BH + rB * 128;
    const int cq = lane & 3;
    const int cbase = (w >> 2) * 32;

    for (int t = blockIdx.x; t < ntiles; t += 148) {
        int n0 = t * 128;
        __syncthreads();
        #pragma unroll
        for (int j = 0; j < 4; j++) {
            int idx = tid + j * 256;
            int e = idx >> 3;
            int cj = idx & 7;
            float4 v0, v1;
            if (n0 + e < n_nodes) {
                const float4* src = (const float4*)x + (size_t)(n0 + e) * 16 + cj * 2;
                v0 = src[0]; v1 = src[1];
            } else {
                v0 = make_float4(0.f, 0.f, 0.f, 0.f);
                v1 = v0;
            }
            float vv[8] = {v0.x, v0.y, v0.z, v0.w, v1.x, v1.y, v1.z, v1.w};
            unsigned H[4], L[4];
            #pragma unroll
            for (int p = 0; p < 4; p++) {
                __half h0 = __float2half_rn(vv[2 * p]);
                __half h1 = __float2half_rn(vv[2 * p + 1]);
                __half l0 = __float2half_rn(vv[2 * p] - __half2float(h0));
                __half l1 = __float2half_rn(vv[2 * p + 1] - __half2float(h1));
                H[p] = (unsigned)__half_as_ushort(h0) | ((unsigned)__half_as_ushort(h1) << 16);
                L[p] = (unsigned)__half_as_ushort(l0) | ((unsigned)__half_as_ushort(l1) << 16);
            }
            unsigned dst = e * 128 + ((cj * 16) ^ ((e & 7) << 4));
            *(uint4*)(smc + NO_AH + dst) = make_uint4(H[0], H[1], H[2], H[3]);
            *(uint4*)(smc + NO_AL + dst) = make_uint4(L[0], L[1], L[2], L[3]);
        }
        __syncthreads();

        float acc[2][8][4];
        #pragma unroll
        for (int mt = 0; mt < 2; mt++)
            #pragma unroll
            for (int nt = 0; nt < 8; nt++)
                #pragma unroll
                for (int p = 0; p < 4; p++) acc[mt][nt][p] = 0.0f;

        const unsigned aoff0 = sb + NO_AH + rA0 * 128;
        const unsigned aoff1 = aoff0 + 16 * 128;
        #pragma unroll
        for (int kc = 0; kc < 4; kc++) {
            unsigned ka = (unsigned)(kc * 32 + hiA) ^ swA;
            unsigned ah[4], ah2[4], al[4], al2[4];
            LDSM4(ah,  aoff0 + ka);
            LDSM4(ah2, aoff1 + ka);
            LDSM4(al,  aoff0 + ka + 16384);
            LDSM4(al2, aoff1 + ka + 16384);
            unsigned kb = (unsigned)(kc * 32 + hiB) ^ swB;
            #pragma unroll
            for (int nt = 0; nt < 8; nt++) {
                unsigned ba = boff + nt * 8 * 128 + kb;
                unsigned bh0, bh1, bl0, bl1;
                LDSM2(bh0, bh1, ba);
                LDSM2(bl0, bl1, ba + 16384);
                MMA16816(acc[0][nt], ah,  bh0, bh1);
                MMA16816(acc[1][nt], ah2, bh0, bh1);
                MMA16816(acc[0][nt], ah,  bl0, bl1);
                MMA16816(acc[1][nt], ah2, bl0, bl1);
                MMA16816(acc[0][nt], al,  bh0, bh1);
                MMA16816(acc[1][nt], al2, bh0, bh1);
            }
        }

        #pragma unroll
        for (int mt = 0; mt < 2; mt++) {
            int elo = m0 + mt * 16 + (lane >> 2);
            int ehi = elo + 8;
            #pragma unroll
            for (int nt = 0; nt < 8; nt++) {
                int c = cbase + nt * 4 + cq;
                if (n0 + elo < n_nodes)
                    *(unsigned*)(P + (size_t)(n0 + elo) * 128 + 2 * c) = pack_f16x2(acc[mt][nt][0], acc[mt][nt][1]);
                if (n0 + ehi < n_nodes)
                    *(unsigned*)(P + (size_t)(n0 + ehi) * 128 + 2 * c) = pack_f16x2(acc[mt][nt][2], acc[mt][nt][3]);
            }
        }
    }
}

// ---------------- edge kernel: 512 threads, B fragments in registers ----------------
__global__ __launch_bounds__(512, 1)
void edge_mma_kernel(const float* __restrict__ ea,
                     const float* __restrict__ bfb,
                     const float* __restrict__ bsb,
                     const int*   __restrict__ esrc,
                     const int*   __restrict__ etgt,
                     int n_edges, int ntiles)
{
    extern __shared__ char smc[];
    unsigned sb = smem_u32(smc);
    int* s_src = (int*)(smc + EO_SRC);
    int* s_tgt = (int*)(smc + EO_TGT);
    float* s_bf = (float*)(smc + EO_BF);
    float* s_bs = (float*)(smc + EO_BS);
    unsigned* stage = (unsigned*)(smc + EO_STAGE);
    const int tid = threadIdx.x;
    const int w = tid >> 5;
    const int lane = tid & 31;
    const int mg = w >> 2;            // 0..3
    const int nq = w & 3;             // 0..3
    const int m0 = mg * 32;

    // ---- startup: stage B (slice 2) into overlay smem ----
    {
        const uint4* bh = (const uint4*)g_Bh + 2 * 1024;
        const uint4* bl = (const uint4*)g_Bl + 2 * 1024;
        #pragma unroll
        for (int j = 0; j < 2; j++) {
            int idx = tid + j * 512;
            int n = idx >> 3;
            int cj = idx & 7;
            unsigned dst = n * 128 + ((cj * 16) ^ ((n & 7) << 4));
            *(uint4*)(smc + EO_BSTG + dst) = bh[idx];
            *(uint4*)(smc + EO_BSTG + 16384 + dst) = bl[idx];
        }
    }
    if (tid < DCH) { s_bf[tid] = bfb[tid]; s_bs[tid] = bsb[tid]; }
    __syncthreads();

    // ---- B fragments to registers (once) ----
    unsigned bh_fr[4][4][2], bl_fr[4][4][2];
    {
        const unsigned hiB = ((lane >> 3) & 1) << 4;
        const unsigned swB = (lane & 7) << 4;
        const unsigned bbase = sb + EO_BSTG + (unsigned)(nq * 32 + (lane & 7)) * 128;
        #pragma unroll
        for (int kc = 0; kc < 4; kc++) {
            unsigned kb = (unsigned)(kc * 32 + hiB) ^ swB;
            #pragma unroll
            for (int nt = 0; nt < 4; nt++) {
                unsigned ba = bbase + nt * 8 * 128 + kb;
                LDSM2(bh_fr[kc][nt][0], bh_fr[kc][nt][1], ba);
                LDSM2(bl_fr[kc][nt][0], bl_fr[kc][nt][1], ba + 16384);
            }
        }
    }
    __syncthreads();   // overlay region now free for stage

    const int rA0 = m0 + (lane & 15);
    const unsigned hiA = ((lane >> 4) & 1) << 4;
    const unsigned swA = (rA0 & 7) << 4;
    const unsigned aoff0 = sb + EO_AH + rA0 * 128;
    const unsigned aoff1 = aoff0 + 16 * 128;
    const int cq = lane & 3;
    const int li = lane & 7;
    const int egl = lane >> 3;

    for (int t = blockIdx.x; t < ntiles; t += gridDim.x) {
        const int e0 = t * TILE_E;

        // ---- A tile fill (512 threads, 2 chunks each) ----
        #pragma unroll
        for (int j = 0; j < 2; j++) {
            int idx = tid + j * 512;
            int e = idx >> 3;
            int cj = idx & 7;
            int ge = e0 + e;
            float4 v0, v1;
            if (ge < n_edges) {
                const float4* src = (const float4*)ea + (size_t)ge * 16 + cj * 2;
                v0 = src[0]; v1 = src[1];
            } else {
                v0 = make_float4(0.f, 0.f, 0.f, 0.f);
                v1 = v0;
            }
            unsigned H[4];
            H[0] = pack_f16x2(v0.x, v0.y);
            H[1] = pack_f16x2(v0.z, v0.w);
            H[2] = pack_f16x2(v1.x, v1.y);
            H[3] = pack_f16x2(v1.z, v1.w);
            unsigned dst = e * 128 + ((cj * 16) ^ ((e & 7) << 4));
            *(uint4*)(smc + EO_AH + dst) = make_uint4(H[0], H[1], H[2], H[3]);
        }
        if (tid < TILE_E) {
            int ge = e0 + tid;
            s_src[tid] = (ge < n_edges) ? esrc[ge] : 0;
            s_tgt[tid] = (ge < n_edges) ? etgt[ge] : 0;
        }
        __syncthreads();

        // ---- mma mainloop: A LDSM only, B from registers ----
        float acc[2][4][4];
        #pragma unroll
        for (int mt = 0; mt < 2; mt++)
            #pragma unroll
            for (int nt = 0; nt < 4; nt++)
                #pragma unroll
                for (int p = 0; p < 4; p++) acc[mt][nt][p] = 0.0f;

        #pragma unroll
        for (int kc = 0; kc < 4; kc++) {
            unsigned ka = (unsigned)(kc * 32 + hiA) ^ swA;
            unsigned ah[4], ah2[4];
            LDSM4(ah,  aoff0 + ka);
            LDSM4(ah2, aoff1 + ka);
            #pragma unroll
            for (int nt = 0; nt < 4; nt++) {
                MMA16816(acc[0][nt], ah,  bh_fr[kc][nt][0], bh_fr[kc][nt][1]);
                MMA16816(acc[1][nt], ah2, bh_fr[kc][nt][0], bh_fr[kc][nt][1]);
                MMA16816(acc[0][nt], ah,  bl_fr[kc][nt][0], bl_fr[kc][nt][1]);
                MMA16816(acc[1][nt], ah2, bl_fr[kc][nt][0], bl_fr[kc][nt][1]);
            }
        }

        // ---- stage raw (g,v) as packed fp16 ----
        #pragma unroll
        for (int mt = 0; mt < 2; mt++) {
            int elo = m0 + mt * 16 + (lane >> 2);
            int ehi = elo + 8;
            #pragma unroll
            for (int nt = 0; nt < 4; nt++) {
                int c = nq * 16 + nt * 4 + cq;
                stage[elo * STGU + c] = pack_f16x2(acc[mt][nt][0], acc[mt][nt][1]);
                stage[ehi * STGU + c] = pack_f16x2(acc[mt][nt][2], acc[mt][nt][3]);
            }
        }
        __syncthreads();

        // ---- per-edge epilogue: 16 warps x 8 edges ----
        #pragma unroll
        for (int g2 = 0; g2 < 2; g2++) {
            int el = w * 8 + g2 * 4 + egl;
            int ge = e0 + el;
            int src = s_src[el];
            int tgt = s_tgt[el];
            const unsigned short* P1r = g_P1h + (size_t)src * 128;
            const unsigned short* P2r = g_P2h + (size_t)tgt * 128;
            #pragma unroll
            for (int q = 0; q < 2; q++) {
                int cc = q * 32 + li * 4;
                uint4 st = *(const uint4*)(stage + el * STGU + cc);
                uint4 p1 = *(const uint4*)(P1r + 2 * cc);
                uint4 p2 = *(const uint4*)(P2r + 2 * cc);
                float4 bfv = *(const float4*)(s_bf + cc);
                float4 bsv = *(const float4*)(s_bs + cc);
                float2 s0 = unpack_h2(st.x), s1 = unpack_h2(st.y), s2 = unpack_h2(st.z), s3 = unpack_h2(st.w);
                float2 q10 = unpack_h2(p1.x), q11 = unpack_h2(p1.y), q12 = unpack_h2(p1.z), q13 = unpack_h2(p1.w);
                float2 q20 = unpack_h2(p2.x), q21 = unpack_h2(p2.y), q22 = unpack_h2(p2.z), q23 = unpack_h2(p2.w);
                float m0v = sigmoid_f(s0.x + q10.x + q20.x + bfv.x) * softplus_f(s0.y + q10.y + q20.y + bsv.x);
                float m1v = sigmoid_f(s1.x + q11.x + q21.x + bfv.y) * softplus_f(s1.y + q11.y + q21.y + bsv.y);
                float m2v = sigmoid_f(s2.x + q12.x + q22.x + bfv.z) * softplus_f(s2.y + q12.y + q22.y + bsv.z);
                float m3v = sigmoid_f(s3.x + q13.x + q23.x + bfv.w) * softplus_f(s3.y + q13.y + q23.y + bsv.w);
                if (ge < n_edges) {
                    float* dst = g_message + (size_t)src * 64 + cc;
                    asm volatile("red.global.add.v4.f32 [%0], {%1, %2, %3, %4};"
                                 :: "l"(dst), "f"(m0v), "f"(m1v), "f"(m2v), "f"(m3v)
                                 : "memory");
                }
            }
        }
        __syncthreads();   // protect stage/s_src before next tile's fill
    }
}

// ---------------- stats ----------------
__global__ __launch_bounds__(256)
void stats_kernel(int n4) {
    int t = blockIdx.x * blockDim.x + threadIdx.x;
    int stride = gridDim.x * blockDim.x;
    const float4* m4 = (const float4*)g_message;
    float4 s = make_float4(0.f, 0.f, 0.f, 0.f);
    float4 q = make_float4(0.f, 0.f, 0.f, 0.f);
    for (int i = t; i < n4; i += stride) {
        float4 v = m4[i];
        s.x += v.x; s.y += v.y; s.z += v.z; s.w += v.w;
        q.x += v.x * v.x; q.y += v.y * v.y; q.z += v.z * v.z; q.w += v.w * v.w;
    }
    __shared__ float4 ss[256];
    __shared__ float4 qq[256];
    ss[threadIdx.x] = s;
    qq[threadIdx.x] = q;
    __syncthreads();
    #pragma unroll
    for (int off = 128; off >= 16; off >>= 1) {
        if (threadIdx.x < off) {
            float4 a = ss[threadIdx.x + off], b = qq[threadIdx.x + off];
            float4 sa = ss[threadIdx.x], qa = qq[threadIdx.x];
            sa.x += a.x; sa.y += a.y; sa.z += a.z; sa.w += a.w;
            qa.x += b.x; qa.y += b.y; qa.z += b.z; qa.w += b.w;
            ss[threadIdx.x] = sa;
            qq[threadIdx.x] = qa;
        }
        __syncthreads();
    }
    if (threadIdx.x < 16) {
        int c = threadIdx.x * 4;
        float4 sa = ss[threadIdx.x], qa = qq[threadIdx.x];
        atomicAdd(&g_sum[c + 0], sa.x); atomicAdd(&g_sum[c + 1], sa.y);
        atomicAdd(&g_sum[c + 2], sa.z); atomicAdd(&g_sum[c + 3], sa.w);
        atomicAdd(&g_sumsq[c + 0], qa.x); atomicAdd(&g_sumsq[c + 1], qa.y);
        atomicAdd(&g_sumsq[c + 2], qa.z); atomicAdd(&g_sumsq[c + 3], qa.w);
    }
}

// ---------------- final ----------------
__global__ __launch_bounds__(256)
void final_kernel(const float* __restrict__ x,
                  const float* __restrict__ gamma,
                  const float* __restrict__ beta,
                  float* __restrict__ out,
                  int n4, float inv_n)
{
    int i = blockIdx.x * blockDim.x + threadIdx.x;
    if (i >= n4) return;
    int c = (i & 15) * 4;
    float4 mm = ((const float4*)g_message)[i];
    float4 xx = ((const float4*)x)[i];
    float4 gm = ((const float4*)gamma)[i & 15];
    float4 bt = ((const float4*)beta)[i & 15];
    float mv[4] = {mm.x, mm.y, mm.z, mm.w};
    float xv[4] = {xx.x, xx.y, xx.z, xx.w};
    float gv[4] = {gm.x, gm.y, gm.z, gm.w};
    float bv[4] = {bt.x, bt.y, bt.z, bt.w};
    float ov[4];
    #pragma unroll
    for (int j = 0; j < 4; j++) {
        float mean = g_sum[c + j] * inv_n;
        float var  = g_sumsq[c + j] * inv_n - mean * mean;
        float inv_std = rsqrtf(var + 1e-5f);
        float mn = (mv[j] - mean) * inv_std * gv[j] + bv[j];
        float t = xv[j] + mn;
        ov[j] = fmaxf(t, 0.0f) + log1pf(expf(-fabsf(t)));
    }
    ((float4*)out)[i] = make_float4(ov[0], ov[1], ov[2], ov[3]);
}

extern "C" void kernel_launch(void* const* d_in, const int* in_sizes, int n_in,
                              void* d_out, int out_size)
{
    const float* x     = (const float*)d_in[0];
    const float* ea    = (const float*)d_in[1];
    const float* Wf    = (const float*)d_in[2];
    const float* bf    = (const float*)d_in[3];
    const float* Ws    = (const float*)d_in[4];
    const float* bs    = (const float*)d_in[5];
    const float* gamma = (const float*)d_in[6];
    const float* beta  = (const float*)d_in[7];
    const int*   esrc  = (const int*)d_in[8];
    const int*   etgt  = (const int*)d_in[9];
    float* out = (float*)d_out;

    int n_nodes = in_sizes[0] / DCH;
    int n_edges = in_sizes[8];
    int total   = n_nodes * DCH;
    int total4  = total / 4;
    int etiles  = (n_edges + TILE_E - 1) / TILE_E;
    int ntiles  = (n_nodes + 127) / 128;

    static bool attr_set = false;
    if (!attr_set) {
        cudaFuncSetAttribute(edge_mma_kernel, cudaFuncAttributeMaxDynamicSharedMemorySize, EDGE_SMEM_BYTES);
        cudaFuncSetAttribute(node_mma_kernel, cudaFuncAttributeMaxDynamicSharedMemorySize, NODE_SMEM_BYTES);
        attr_set = true;
    }

    {   // 1
        int grid = (total4 + 255) / 256;
        if (grid > 1024) grid = 1024;
        zero_kernel<<<grid, 256>>>(total4);
    }
    prep_B_kernel<<<96, 256>>>(Wf, Ws);                                      // 2
    {   // 3
        dim3 grid(148, 2);
        node_mma_kernel<<<grid, 256, NODE_SMEM_BYTES>>>(x, n_nodes, ntiles);
    }
    {   // 4  <- ncu slot
        int grid = 148;
        if (grid > etiles) grid = etiles;
        edge_mma_kernel<<<grid, 512, EDGE_SMEM_BYTES>>>(ea, bf, bs, esrc, etgt, n_edges, etiles);
    }
    stats_kernel<<<512, 256>>>(total4);                                      // 5
    {   // 6
        int grid = (total4 + 255) / 256;
        final_kernel<<<grid, 256>>>(x, gamma, beta, out, total4, 1.0f / (float)n_nodes);
    }
}

// round 11
// speedup vs baseline: 1.1220x; 1.1220x over previous
#include <cuda_runtime.h>
#include <cuda_fp16.h>
#include <math.h>

#define DCH    64
#define FAN    192
#define TILE_E 64
#define MAX_NODES 50176

__device__ float g_message[MAX_NODES * DCH];
__device__ unsigned short g_P1h[MAX_NODES * 128];
__device__ unsigned short g_P2h[MAX_NODES * 128];
__device__ float g_sum[DCH];
__device__ float g_sumsq[DCH];
__device__ unsigned short g_Bh[3 * 128 * 64];
__device__ unsigned short g_Bl[3 * 128 * 64];

// ---------------- edge kernel smem (bytes) ----------------
#define EO_SRC   0                 // 256 B
#define EO_TGT   256
#define EO_BF    512
#define EO_BS    768
#define EO_AH    1024              // 64*128 = 8192 B
#define EO_STAGE 9216              // 64 rows x 68 u32 = 17408 B
#define STGU     68
#define EDGE_SMEM_BYTES 26624

// ---------------- node kernel smem ----------------
#define NO_AH    0
#define NO_AL    16384
#define NO_BH    32768
#define NO_BL    49152
#define NODE_SMEM_BYTES 65536

// ---------------- helpers ----------------
__device__ __forceinline__ unsigned smem_u32(const void* p) {
    unsigned a;
    asm("{ .reg .u64 t; cvta.to.shared.u64 t, %1; cvt.u32.u64 %0, t; }" : "=r"(a) : "l"(p));
    return a;
}
__device__ __forceinline__ unsigned pack_f16x2(float lo, float hi) {
    unsigned r;
    asm("cvt.rn.f16x2.f32 %0, %1, %2;" : "=r"(r) : "f"(hi), "f"(lo));
    return r;
}
__device__ __forceinline__ float2 unpack_h2(unsigned u) {
    __half2 h = *reinterpret_cast<__half2*>(&u);
    return __half22float2(h);
}
__device__ __forceinline__ float ex2a(float x) { float r; asm("ex2.approx.f32 %0, %1;" : "=f"(r) : "f"(x)); return r; }
__device__ __forceinline__ float lg2a(float x) { float r; asm("lg2.approx.f32 %0, %1;" : "=f"(r) : "f"(x)); return r; }
__device__ __forceinline__ float rcpa(float x) { float r; asm("rcp.approx.f32 %0, %1;" : "=f"(r) : "f"(x)); return r; }
__device__ __forceinline__ float sigmoid_f(float g) {
    return rcpa(1.0f + ex2a(-1.44269504f * g));
}
__device__ __forceinline__ float softplus_f(float v) {
    float u = ex2a(-1.44269504f * fabsf(v));
    return fmaxf(v, 0.0f) + 0.69314718f * lg2a(1.0f + u);
}

#define LDSM4(R, A) \
    asm volatile("ldmatrix.sync.aligned.m8n8.x4.shared.b16 {%0,%1,%2,%3}, [%4];" \
        : "=r"((R)[0]), "=r"((R)[1]), "=r"((R)[2]), "=r"((R)[3]) : "r"(A))
#define LDSM2(R0, R1, A) \
    asm volatile("ldmatrix.sync.aligned.m8n8.x2.shared.b16 {%0,%1}, [%2];" \
        : "=r"(R0), "=r"(R1) : "r"(A))
#define MMA16816(D, A, B0, B1) \
    asm volatile("mma.sync.aligned.m16n8k16.row.col.f32.f16.f16.f32 " \
        "{%0,%1,%2,%3}, {%4,%5,%6,%7}, {%8,%9}, {%0,%1,%2,%3};" \
        : "+f"((D)[0]), "+f"((D)[1]), "+f"((D)[2]), "+f"((D)[3]) \
        : "r"((A)[0]), "r"((A)[1]), "r"((A)[2]), "r"((A)[3]), "r"(B0), "r"(B1))

// ---------------- prep: all 3 W slices -> fp16 hi/lo ----------------
__global__ void prep_B_kernel(const float* __restrict__ Wf, const float* __restrict__ Ws) {
    int idx = blockIdx.x * 256 + threadIdx.x;   // 24576
    int s = idx >> 13;
    int r = idx & 8191;
    int n = r >> 6;
    int k = r & 63;
    int d = n >> 1;
    const float* w = (n & 1) ? Ws : Wf;
    float v = w[d * FAN + s * 64 + k];
    __half h = __float2half_rn(v);
    __half l = __float2half_rn(v - __half2float(h));
    g_Bh[idx] = __half_as_ushort(h);
    g_Bl[idx] = __half_as_ushort(l);
}

// ---------------- zero ----------------
__global__ void zero_kernel(int total4) {
    int i = blockIdx.x * blockDim.x + threadIdx.x;
    int stride = gridDim.x * blockDim.x;
    float4* m4 = (float4*)g_message;
    for (int j = i; j < total4; j += stride) m4[j] = make_float4(0.f, 0.f, 0.f, 0.f);
    if (i < DCH) { g_sum[i] = 0.0f; g_sumsq[i] = 0.0f; }
}

// ---------------- node projections on tensor cores -> fp16 P ----------------
__global__ __launch_bounds__(256, 2)
void node_mma_kernel(const float* __restrict__ x, int n_nodes, int ntiles)
{
    extern __shared__ char smc[];
    unsigned sb = smem_u32(smc);
    const int tid = threadIdx.x;
    const int wsel = blockIdx.y;
    unsigned short* P = wsel ? g_P2h : g_P1h;

    {
        const uint4* bh = (const uint4*)g_Bh + wsel * 1024;
        const uint4* bl = (const uint4*)g_Bl + wsel * 1024;
        #pragma unroll
        for (int j = 0; j < 4; j++) {
            int idx = tid + j * 256;
            int n = idx >> 3;
            int cj = idx & 7;
            unsigned dst = n * 128 + ((cj * 16) ^ ((n & 7) << 4));
            *(uint4*)(smc + NO_BH + dst) = bh[idx];
            *(uint4*)(smc + NO_BL + dst) = bl[idx];
        }
    }

    const int w = tid >> 5;
    const int lane = tid & 31;
    const int m0 = (w & 3) * 32;
    const int nn0 = (w >> 2) * 64;
    const int rA0 = m0 + (lane & 15);
    const unsigned hiA = ((lane >> 4) & 1) << 4;
    const unsigned swA = (rA0 & 7) << 4;
    const int rB = nn0 + (lane & 7);
    const unsigned hiB = ((lane >> 3) & 1) << 4;
    const unsigned swB = (lane & 7) << 4;
    const unsigned boff = sb + NO_BH + rB * 128;
    const int cq = lane & 3;
    const int cbase = (w >> 2) * 32;

    for (int t = blockIdx.x; t < ntiles; t += 148) {
        int n0 = t * 128;
        __syncthreads();
        #pragma unroll
        for (int j = 0; j < 4; j++) {
            int idx = tid + j * 256;
            int e = idx >> 3;
            int cj = idx & 7;
            float4 v0, v1;
            if (n0 + e < n_nodes) {
                const float4* src = (const float4*)x + (size_t)(n0 + e) * 16 + cj * 2;
                v0 = src[0]; v1 = src[1];
            } else {
                v0 = make_float4(0.f, 0.f, 0.f, 0.f);
                v1 = v0;
            }
            float vv[8] = {v0.x, v0.y, v0.z, v0.w, v1.x, v1.y, v1.z, v1.w};
            unsigned H[4], L[4];
            #pragma unroll
            for (int p = 0; p < 4; p++) {
                __half h0 = __float2half_rn(vv[2 * p]);
                __half h1 = __float2half_rn(vv[2 * p + 1]);
                __half l0 = __float2half_rn(vv[2 * p] - __half2float(h0));
                __half l1 = __float2half_rn(vv[2 * p + 1] - __half2float(h1));
                H[p] = (unsigned)__half_as_ushort(h0) | ((unsigned)__half_as_ushort(h1) << 16);
                L[p] = (unsigned)__half_as_ushort(l0) | ((unsigned)__half_as_ushort(l1) << 16);
            }
            unsigned dst = e * 128 + ((cj * 16) ^ ((e & 7) << 4));
            *(uint4*)(smc + NO_AH + dst) = make_uint4(H[0], H[1], H[2], H[3]);
            *(uint4*)(smc + NO_AL + dst) = make_uint4(L[0], L[1], L[2], L[3]);
        }
        __syncthreads();

        float acc[2][8][4];
        #pragma unroll
        for (int mt = 0; mt < 2; mt++)
            #pragma unroll
            for (int nt = 0; nt < 8; nt++)
                #pragma unroll
                for (int p = 0; p < 4; p++) acc[mt][nt][p] = 0.0f;

        const unsigned aoff0 = sb + NO_AH + rA0 * 128;
        const unsigned aoff1 = aoff0 + 16 * 128;
        #pragma unroll
        for (int kc = 0; kc < 4; kc++) {
            unsigned ka = (unsigned)(kc * 32 + hiA) ^ swA;
            unsigned ah[4], ah2[4], al[4], al2[4];
            LDSM4(ah,  aoff0 + ka);
            LDSM4(ah2, aoff1 + ka);
            LDSM4(al,  aoff0 + ka + 16384);
            LDSM4(al2, aoff1 + ka + 16384);
            unsigned kb = (unsigned)(kc * 32 + hiB) ^ swB;
            #pragma unroll
            for (int nt = 0; nt < 8; nt++) {
                unsigned ba = boff + nt * 8 * 128 + kb;
                unsigned bh0, bh1, bl0, bl1;
                LDSM2(bh0, bh1, ba);
                LDSM2(bl0, bl1, ba + 16384);
                MMA16816(acc[0][nt], ah,  bh0, bh1);
                MMA16816(acc[1][nt], ah2, bh0, bh1);
                MMA16816(acc[0][nt], ah,  bl0, bl1);
                MMA16816(acc[1][nt], ah2, bl0, bl1);
                MMA16816(acc[0][nt], al,  bh0, bh1);
                MMA16816(acc[1][nt], al2, bh0, bh1);
            }
        }

        #pragma unroll
        for (int mt = 0; mt < 2; mt++) {
            int elo = m0 + mt * 16 + (lane >> 2);
            int ehi = elo + 8;
            #pragma unroll
            for (int nt = 0; nt < 8; nt++) {
                int c = cbase + nt * 4 + cq;
                if (n0 + elo < n_nodes)
                    *(unsigned*)(P + (size_t)(n0 + elo) * 128 + 2 * c) = pack_f16x2(acc[mt][nt][0], acc[mt][nt][1]);
                if (n0 + ehi < n_nodes)
                    *(unsigned*)(P + (size_t)(n0 + ehi) * 128 + 2 * c) = pack_f16x2(acc[mt][nt][2], acc[mt][nt][3]);
            }
        }
    }
}

// ---------------- edge kernel: 256 threads, 64-edge tile, B frags from gmem ----------------
__global__ __launch_bounds__(256, 2)
void edge_mma_kernel(const float* __restrict__ ea,
                     const float* __restrict__ bfb,
                     const float* __restrict__ bsb,
                     const int*   __restrict__ esrc,
                     const int*   __restrict__ etgt,
                     int n_edges, int ntiles)
{
    extern __shared__ char smc[];
    unsigned sb = smem_u32(smc);
    int* s_src = (int*)(smc + EO_SRC);
    int* s_tgt = (int*)(smc + EO_TGT);
    float* s_bf = (float*)(smc + EO_BF);
    float* s_bs = (float*)(smc + EO_BS);
    unsigned* stage = (unsigned*)(smc + EO_STAGE);
    const int tid = threadIdx.x;
    const int w = tid >> 5;
    const int lane = tid & 31;
    const int mg = w >> 2;            // 0..1
    const int nq = w & 3;             // 0..3
    const int m0 = mg * 32;

    if (tid < DCH) { s_bf[tid] = bfb[tid]; s_bs[tid] = bsb[tid]; }

    // ---- B fragments straight from gmem (once); layout per mma m16n8k16 .col ----
    unsigned bh_fr[4][4][2], bl_fr[4][4][2];
    {
        const unsigned short* BH = g_Bh + 2 * 8192;
        const unsigned short* BL = g_Bl + 2 * 8192;
        int nrow = nq * 32 + (lane >> 2);
        int k0 = (lane & 3) * 2;
        #pragma unroll
        for (int kc = 0; kc < 4; kc++) {
            #pragma unroll
            for (int nt = 0; nt < 4; nt++) {
                int off = (nrow + nt * 8) * 64 + kc * 16 + k0;
                bh_fr[kc][nt][0] = *(const unsigned*)(BH + off);
                bh_fr[kc][nt][1] = *(const unsigned*)(BH + off + 8);
                bl_fr[kc][nt][0] = *(const unsigned*)(BL + off);
                bl_fr[kc][nt][1] = *(const unsigned*)(BL + off + 8);
            }
        }
    }

    const int rA0 = m0 + (lane & 15);
    const unsigned hiA = ((lane >> 4) & 1) << 4;
    const unsigned swA = (rA0 & 7) << 4;
    const unsigned aoff0 = sb + EO_AH + rA0 * 128;
    const unsigned aoff1 = aoff0 + 16 * 128;
    const int cq = lane & 3;
    const int li = lane & 7;
    const int egl = lane >> 3;

    __syncthreads();   // bias visible

    for (int t = blockIdx.x; t < ntiles; t += gridDim.x) {
        const int e0 = t * TILE_E;

        // ---- A tile fill: 64 edges x 8 chunks = 512, 2 per thread ----
        #pragma unroll
        for (int j = 0; j < 2; j++) {
            int idx = tid + j * 256;
            int e = idx >> 3;
            int cj = idx & 7;
            int ge = e0 + e;
            float4 v0, v1;
            if (ge < n_edges) {
                const float4* src = (const float4*)ea + (size_t)ge * 16 + cj * 2;
                v0 = src[0]; v1 = src[1];
            } else {
                v0 = make_float4(0.f, 0.f, 0.f, 0.f);
                v1 = v0;
            }
            unsigned H[4];
            H[0] = pack_f16x2(v0.x, v0.y);
            H[1] = pack_f16x2(v0.z, v0.w);
            H[2] = pack_f16x2(v1.x, v1.y);
            H[3] = pack_f16x2(v1.z, v1.w);
            unsigned dst = e * 128 + ((cj * 16) ^ ((e & 7) << 4));
            *(uint4*)(smc + EO_AH + dst) = make_uint4(H[0], H[1], H[2], H[3]);
        }
        if (tid < TILE_E) {
            int ge = e0 + tid;
            s_src[tid] = (ge < n_edges) ? esrc[ge] : 0;
            s_tgt[tid] = (ge < n_edges) ? etgt[ge] : 0;
        }
        __syncthreads();

        // ---- mma mainloop: A LDSM only, B from registers ----
        float acc[2][4][4];
        #pragma unroll
        for (int mt = 0; mt < 2; mt++)
            #pragma unroll
            for (int nt = 0; nt < 4; nt++)
                #pragma unroll
                for (int p = 0; p < 4; p++) acc[mt][nt][p] = 0.0f;

        #pragma unroll
        for (int kc = 0; kc < 4; kc++) {
            unsigned ka = (unsigned)(kc * 32 + hiA) ^ swA;
            unsigned ah[4], ah2[4];
            LDSM4(ah,  aoff0 + ka);
            LDSM4(ah2, aoff1 + ka);
            #pragma unroll
            for (int nt = 0; nt < 4; nt++) {
                MMA16816(acc[0][nt], ah,  bh_fr[kc][nt][0], bh_fr[kc][nt][1]);
                MMA16816(acc[1][nt], ah2, bh_fr[kc][nt][0], bh_fr[kc][nt][1]);
                MMA16816(acc[0][nt], ah,  bl_fr[kc][nt][0], bl_fr[kc][nt][1]);
                MMA16816(acc[1][nt], ah2, bl_fr[kc][nt][0], bl_fr[kc][nt][1]);
            }
        }

        // ---- stage raw (g,v) as packed fp16 ----
        #pragma unroll
        for (int mt = 0; mt < 2; mt++) {
            int elo = m0 + mt * 16 + (lane >> 2);
            int ehi = elo + 8;
            #pragma unroll
            for (int nt = 0; nt < 4; nt++) {
                int c = nq * 16 + nt * 4 + cq;
                stage[elo * STGU + c] = pack_f16x2(acc[mt][nt][0], acc[mt][nt][1]);
                stage[ehi * STGU + c] = pack_f16x2(acc[mt][nt][2], acc[mt][nt][3]);
            }
        }
        __syncthreads();

        // ---- per-edge epilogue: 8 warps x 8 edges ----
        #pragma unroll
        for (int g2 = 0; g2 < 2; g2++) {
            int el = w * 8 + g2 * 4 + egl;
            int ge = e0 + el;
            int src = s_src[el];
            int tgt = s_tgt[el];
            const unsigned short* P1r = g_P1h + (size_t)src * 128;
            const unsigned short* P2r = g_P2h + (size_t)tgt * 128;
            #pragma unroll
            for (int q = 0; q < 2; q++) {
                int cc = q * 32 + li * 4;
                uint4 st = *(const uint4*)(stage + el * STGU + cc);
                uint4 p1 = *(const uint4*)(P1r + 2 * cc);
                uint4 p2 = *(const uint4*)(P2r + 2 * cc);
                float4 bfv = *(const float4*)(s_bf + cc);
                float4 bsv = *(const float4*)(s_bs + cc);
                float2 s0 = unpack_h2(st.x), s1 = unpack_h2(st.y), s2 = unpack_h2(st.z), s3 = unpack_h2(st.w);
                float2 q10 = unpack_h2(p1.x), q11 = unpack_h2(p1.y), q12 = unpack_h2(p1.z), q13 = unpack_h2(p1.w);
                float2 q20 = unpack_h2(p2.x), q21 = unpack_h2(p2.y), q22 = unpack_h2(p2.z), q23 = unpack_h2(p2.w);
                float m0v = sigmoid_f(s0.x + q10.x + q20.x + bfv.x) * softplus_f(s0.y + q10.y + q20.y + bsv.x);
                float m1v = sigmoid_f(s1.x + q11.x + q21.x + bfv.y) * softplus_f(s1.y + q11.y + q21.y + bsv.y);
                float m2v = sigmoid_f(s2.x + q12.x + q22.x + bfv.z) * softplus_f(s2.y + q12.y + q22.y + bsv.z);
                float m3v = sigmoid_f(s3.x + q13.x + q23.x + bfv.w) * softplus_f(s3.y + q13.y + q23.y + bsv.w);
                if (ge < n_edges) {
                    float* dst = g_message + (size_t)src * 64 + cc;
                    asm volatile("red.global.add.v4.f32 [%0], {%1, %2, %3, %4};"
                                 :: "l"(dst), "f"(m0v), "f"(m1v), "f"(m2v), "f"(m3v)
                                 : "memory");
                }
            }
        }
        __syncthreads();   // protect stage/s_src before next tile's fill
    }
}

// ---------------- stats ----------------
__global__ __launch_bounds__(256)
void stats_kernel(int n4) {
    int t = blockIdx.x * blockDim.x + threadIdx.x;
    int stride = gridDim.x * blockDim.x;
    const float4* m4 = (const float4*)g_message;
    float4 s = make_float4(0.f, 0.f, 0.f, 0.f);
    float4 q = make_float4(0.f, 0.f, 0.f, 0.f);
    for (int i = t; i < n4; i += stride) {
        float4 v = m4[i];
        s.x += v.x; s.y += v.y; s.z += v.z; s.w += v.w;
        q.x += v.x * v.x; q.y += v.y * v.y; q.z += v.z * v.z; q.w += v.w * v.w;
    }
    __shared__ float4 ss[256];
    __shared__ float4 qq[256];
    ss[threadIdx.x] = s;
    qq[threadIdx.x] = q;
    __syncthreads();
    #pragma unroll
    for (int off = 128; off >= 16; off >>= 1) {
        if (threadIdx.x < off) {
            float4 a = ss[threadIdx.x + off], b = qq[threadIdx.x + off];
            float4 sa = ss[threadIdx.x], qa = qq[threadIdx.x];
            sa.x += a.x; sa.y += a.y; sa.z += a.z; sa.w += a.w;
            qa.x += b.x; qa.y += b.y; qa.z += b.z; qa.w += b.w;
            ss[threadIdx.x] = sa;
            qq[threadIdx.x] = qa;
        }
        __syncthreads();
    }
    if (threadIdx.x < 16) {
        int c = threadIdx.x * 4;
        float4 sa = ss[threadIdx.x], qa = qq[threadIdx.x];
        atomicAdd(&g_sum[c + 0], sa.x); atomicAdd(&g_sum[c + 1], sa.y);
        atomicAdd(&g_sum[c + 2], sa.z); atomicAdd(&g_sum[c + 3], sa.w);
        atomicAdd(&g_sumsq[c + 0], qa.x); atomicAdd(&g_sumsq[c + 1], qa.y);
        atomicAdd(&g_sumsq[c + 2], qa.z); atomicAdd(&g_sumsq[c + 3], qa.w);
    }
}

// ---------------- final ----------------
__global__ __launch_bounds__(256)
void final_kernel(const float* __restrict__ x,
                  const float* __restrict__ gamma,
                  const float* __restrict__ beta,
                  float* __restrict__ out,
                  int n4, float inv_n)
{
    int i = blockIdx.x * blockDim.x + threadIdx.x;
    if (i >= n4) return;
    int c = (i & 15) * 4;
    float4 mm = ((const float4*)g_message)[i];
    float4 xx = ((const float4*)x)[i];
    float4 gm = ((const float4*)gamma)[i & 15];
    float4 bt = ((const float4*)beta)[i & 15];
    float mv[4] = {mm.x, mm.y, mm.z, mm.w};
    float xv[4] = {xx.x, xx.y, xx.z, xx.w};
    float gv[4] = {gm.x, gm.y, gm.z, gm.w};
    float bv[4] = {bt.x, bt.y, bt.z, bt.w};
    float ov[4];
    #pragma unroll
    for (int j = 0; j < 4; j++) {
        float mean = g_sum[c + j] * inv_n;
        float var  = g_sumsq[c + j] * inv_n - mean * mean;
        float inv_std = rsqrtf(var + 1e-5f);
        float mn = (mv[j] - mean) * inv_std * gv[j] + bv[j];
        float t = xv[j] + mn;
        ov[j] = fmaxf(t, 0.0f) + log1pf(expf(-fabsf(t)));
    }
    ((float4*)out)[i] = make_float4(ov[0], ov[1], ov[2], ov[3]);
}

extern "C" void kernel_launch(void* const* d_in, const int* in_sizes, int n_in,
                              void* d_out, int out_size)
{
    const float* x     = (const float*)d_in[0];
    const float* ea    = (const float*)d_in[1];
    const float* Wf    = (const float*)d_in[2];
    const float* bf    = (const float*)d_in[3];
    const float* Ws    = (const float*)d_in[4];
    const float* bs    = (const float*)d_in[5];
    const float* gamma = (const float*)d_in[6];
    const float* beta  = (const float*)d_in[7];
    const int*   esrc  = (const int*)d_in[8];
    const int*   etgt  = (const int*)d_in[9];
    float* out = (float*)d_out;

    int n_nodes = in_sizes[0] / DCH;
    int n_edges = in_sizes[8];
    int total   = n_nodes * DCH;
    int total4  = total / 4;
    int etiles  = (n_edges + TILE_E - 1) / TILE_E;
    int ntiles  = (n_nodes + 127) / 128;

    static bool attr_set = false;
    if (!attr_set) {
        cudaFuncSetAttribute(edge_mma_kernel, cudaFuncAttributeMaxDynamicSharedMemorySize, EDGE_SMEM_BYTES);
        cudaFuncSetAttribute(node_mma_kernel, cudaFuncAttributeMaxDynamicSharedMemorySize, NODE_SMEM_BYTES);
        attr_set = true;
    }

    {   // 1
        int grid = (total4 + 255) / 256;
        if (grid > 1024) grid = 1024;
        zero_kernel<<<grid, 256>>>(total4);
    }
    prep_B_kernel<<<96, 256>>>(Wf, Ws);                                      // 2
    {   // 3
        dim3 grid(148, 2);
        node_mma_kernel<<<grid, 256, NODE_SMEM_BYTES>>>(x, n_nodes, ntiles);
    }
    {   // 4  <- ncu slot
        int grid = 296;
        if (grid > etiles) grid = etiles;
        edge_mma_kernel<<<grid, 256, EDGE_SMEM_BYTES>>>(ea, bf, bs, esrc, etgt, n_edges, etiles);
    }
    stats_kernel<<<512, 256>>>(total4);                                      // 5
    {   // 6
        int grid = (total4 + 255) / 256;
        final_kernel<<<grid, 256>>>(x, gamma, beta, out, total4, 1.0f / (float)n_nodes);
    }
}

// round 12
// speedup vs baseline: 1.3527x; 1.2056x over previous
#include <cuda_runtime.h>
#include <cuda_fp16.h>
#include <math.h>

#define DCH    64
#define FAN    192
#define TILE_E 64
#define MAX_NODES 50176

__device__ float g_message[MAX_NODES * DCH];
__device__ unsigned short g_P1h[MAX_NODES * 128];
__device__ unsigned short g_P2h[MAX_NODES * 128];
__device__ float g_sum[DCH];
__device__ float g_sumsq[DCH];
__device__ unsigned short g_Bh[3 * 128 * 64];
__device__ unsigned short g_Bl[3 * 128 * 64];

// ---------------- edge kernel smem (bytes) ----------------
#define EO_SRC   0                 // 256 B
#define EO_TGT   256
#define EO_BF    512
#define EO_BS    768
#define EO_AH    1024              // 64*128 = 8192 B
#define EO_STAGE 9216              // 64 rows x 68 u32 = 17408 B
#define STGU     68
#define EO_SP1   26624             // 64 edges x 256 B = 16384
#define EO_SP2   43008             // 16384
#define EDGE_SMEM_BYTES 59392

// ---------------- node kernel smem ----------------
#define NO_AH    0
#define NO_AL    16384
#define NO_BH    32768
#define NO_BL    49152
#define NODE_SMEM_BYTES 65536

// ---------------- helpers ----------------
__device__ __forceinline__ unsigned smem_u32(const void* p) {
    unsigned a;
    asm("{ .reg .u64 t; cvta.to.shared.u64 t, %1; cvt.u32.u64 %0, t; }" : "=r"(a) : "l"(p));
    return a;
}
__device__ __forceinline__ unsigned pack_f16x2(float lo, float hi) {
    unsigned r;
    asm("cvt.rn.f16x2.f32 %0, %1, %2;" : "=r"(r) : "f"(hi), "f"(lo));
    return r;
}
__device__ __forceinline__ float2 unpack_h2(unsigned u) {
    __half2 h = *reinterpret_cast<__half2*>(&u);
    return __half22float2(h);
}
__device__ __forceinline__ float ex2a(float x) { float r; asm("ex2.approx.f32 %0, %1;" : "=f"(r) : "f"(x)); return r; }
__device__ __forceinline__ float lg2a(float x) { float r; asm("lg2.approx.f32 %0, %1;" : "=f"(r) : "f"(x)); return r; }
__device__ __forceinline__ float rcpa(float x) { float r; asm("rcp.approx.f32 %0, %1;" : "=f"(r) : "f"(x)); return r; }
__device__ __forceinline__ float sigmoid_f(float g) {
    return rcpa(1.0f + ex2a(-1.44269504f * g));
}
__device__ __forceinline__ float softplus_f(float v) {
    float u = ex2a(-1.44269504f * fabsf(v));
    return fmaxf(v, 0.0f) + 0.69314718f * lg2a(1.0f + u);
}

#define LDSM4(R, A) \
    asm volatile("ldmatrix.sync.aligned.m8n8.x4.shared.b16 {%0,%1,%2,%3}, [%4];" \
        : "=r"((R)[0]), "=r"((R)[1]), "=r"((R)[2]), "=r"((R)[3]) : "r"(A))
#define LDSM2(R0, R1, A) \
    asm volatile("ldmatrix.sync.aligned.m8n8.x2.shared.b16 {%0,%1}, [%2];" \
        : "=r"(R0), "=r"(R1) : "r"(A))
#define MMA16816(D, A, B0, B1) \
    asm volatile("mma.sync.aligned.m16n8k16.row.col.f32.f16.f16.f32 " \
        "{%0,%1,%2,%3}, {%4,%5,%6,%7}, {%8,%9}, {%0,%1,%2,%3};" \
        : "+f"((D)[0]), "+f"((D)[1]), "+f"((D)[2]), "+f"((D)[3]) \
        : "r"((A)[0]), "r"((A)[1]), "r"((A)[2]), "r"((A)[3]), "r"(B0), "r"(B1))
#define CP_ASYNC16(dst, src) \
    asm volatile("cp.async.cg.shared.global [%0], [%1], 16;" :: "r"(dst), "l"(src))
#define CP_COMMIT() asm volatile("cp.async.commit_group;" ::: "memory")
#define CP_WAIT0()  asm volatile("cp.async.wait_group 0;" ::: "memory")

// ---------------- prep: all 3 W slices -> fp16 hi/lo ----------------
__global__ void prep_B_kernel(const float* __restrict__ Wf, const float* __restrict__ Ws) {
    int idx = blockIdx.x * 256 + threadIdx.x;   // 24576
    int s = idx >> 13;
    int r = idx & 8191;
    int n = r >> 6;
    int k = r & 63;
    int d = n >> 1;
    const float* w = (n & 1) ? Ws : Wf;
    float v = w[d * FAN + s * 64 + k];
    __half h = __float2half_rn(v);
    __half l = __float2half_rn(v - __half2float(h));
    g_Bh[idx] = __half_as_ushort(h);
    g_Bl[idx] = __half_as_ushort(l);
}

// ---------------- zero ----------------
__global__ void zero_kernel(int total4) {
    int i = blockIdx.x * blockDim.x + threadIdx.x;
    int stride = gridDim.x * blockDim.x;
    float4* m4 = (float4*)g_message;
    for (int j = i; j < total4; j += stride) m4[j] = make_float4(0.f, 0.f, 0.f, 0.f);
    if (i < DCH) { g_sum[i] = 0.0f; g_sumsq[i] = 0.0f; }
}

// ---------------- node projections on tensor cores -> fp16 P ----------------
__global__ __launch_bounds__(256, 2)
void node_mma_kernel(const float* __restrict__ x, int n_nodes, int ntiles)
{
    extern __shared__ char smc[];
    unsigned sb = smem_u32(smc);
    const int tid = threadIdx.x;
    const int wsel = blockIdx.y;
    unsigned short* P = wsel ? g_P2h : g_P1h;

    {
        const uint4* bh = (const uint4*)g_Bh + wsel * 1024;
        const uint4* bl = (const uint4*)g_Bl + wsel * 1024;
        #pragma unroll
        for (int j = 0; j < 4; j++) {
            int idx = tid + j * 256;
            int n = idx >> 3;
            int cj = idx & 7;
            unsigned dst = n * 128 + ((cj * 16) ^ ((n & 7) << 4));
            *(uint4*)(smc + NO_BH + dst) = bh[idx];
            *(uint4*)(smc + NO_BL + dst) = bl[idx];
        }
    }

    const int w = tid >> 5;
    const int lane = tid & 31;
    const int m0 = (w & 3) * 32;
    const int nn0 = (w >> 2) * 64;
    const int rA0 = m0 + (lane & 15);
    const unsigned hiA = ((lane >> 4) & 1) << 4;
    const unsigned swA = (rA0 & 7) << 4;
    const int rB = nn0 + (lane & 7);
    const unsigned hiB = ((lane >> 3) & 1) << 4;
    const unsigned swB = (lane & 7) << 4;
    const unsigned boff = sb + NO_BH + rB * 128;
    const int cq = lane & 3;
    const int cbase = (w >> 2) * 32;

    for (int t = blockIdx.x; t < ntiles; t += 148) {
        int n0 = t * 128;
        __syncthreads();
        #pragma unroll
        for (int j = 0; j < 4; j++) {
            int idx = tid + j * 256;
            int e = idx >> 3;
            int cj = idx & 7;
            float4 v0, v1;
            if (n0 + e < n_nodes) {
                const float4* src = (const float4*)x + (size_t)(n0 + e) * 16 + cj * 2;
                v0 = src[0]; v1 = src[1];
            } else {
                v0 = make_float4(0.f, 0.f, 0.f, 0.f);
                v1 = v0;
            }
            float vv[8] = {v0.x, v0.y, v0.z, v0.w, v1.x, v1.y, v1.z, v1.w};
            unsigned H[4], L[4];
            #pragma unroll
            for (int p = 0; p < 4; p++) {
                __half h0 = __float2half_rn(vv[2 * p]);
                __half h1 = __float2half_rn(vv[2 * p + 1]);
                __half l0 = __float2half_rn(vv[2 * p] - __half2float(h0));
                __half l1 = __float2half_rn(vv[2 * p + 1] - __half2float(h1));
                H[p] = (unsigned)__half_as_ushort(h0) | ((unsigned)__half_as_ushort(h1) << 16);
                L[p] = (unsigned)__half_as_ushort(l0) | ((unsigned)__half_as_ushort(l1) << 16);
            }
            unsigned dst = e * 128 + ((cj * 16) ^ ((e & 7) << 4));
            *(uint4*)(smc + NO_AH + dst) = make_uint4(H[0], H[1], H[2], H[3]);
            *(uint4*)(smc + NO_AL + dst) = make_uint4(L[0], L[1], L[2], L[3]);
        }
        __syncthreads();

        float acc[2][8][4];
        #pragma unroll
        for (int mt = 0; mt < 2; mt++)
            #pragma unroll
            for (int nt = 0; nt < 8; nt++)
                #pragma unroll
                for (int p = 0; p < 4; p++) acc[mt][nt][p] = 0.0f;

        const unsigned aoff0 = sb + NO_AH + rA0 * 128;
        const unsigned aoff1 = aoff0 + 16 * 128;
        #pragma unroll
        for (int kc = 0; kc < 4; kc++) {
            unsigned ka = (unsigned)(kc * 32 + hiA) ^ swA;
            unsigned ah[4], ah2[4], al[4], al2[4];
            LDSM4(ah,  aoff0 + ka);
            LDSM4(ah2, aoff1 + ka);
            LDSM4(al,  aoff0 + ka + 16384);
            LDSM4(al2, aoff1 + ka + 16384);
            unsigned kb = (unsigned)(kc * 32 + hiB) ^ swB;
            #pragma unroll
            for (int nt = 0; nt < 8; nt++) {
                unsigned ba = boff + nt * 8 * 128 + kb;
                unsigned bh0, bh1, bl0, bl1;
                LDSM2(bh0, bh1, ba);
                LDSM2(bl0, bl1, ba + 16384);
                MMA16816(acc[0][nt], ah,  bh0, bh1);
                MMA16816(acc[1][nt], ah2, bh0, bh1);
                MMA16816(acc[0][nt], ah,  bl0, bl1);
                MMA16816(acc[1][nt], ah2, bl0, bl1);
                MMA16816(acc[0][nt], al,  bh0, bh1);
                MMA16816(acc[1][nt], al2, bh0, bh1);
            }
        }

        #pragma unroll
        for (int mt = 0; mt < 2; mt++) {
            int elo = m0 + mt * 16 + (lane >> 2);
            int ehi = elo + 8;
            #pragma unroll
            for (int nt = 0; nt < 8; nt++) {
                int c = cbase + nt * 4 + cq;
                if (n0 + elo < n_nodes)
                    *(unsigned*)(P + (size_t)(n0 + elo) * 128 + 2 * c) = pack_f16x2(acc[mt][nt][0], acc[mt][nt][1]);
                if (n0 + ehi < n_nodes)
                    *(unsigned*)(P + (size_t)(n0 + ehi) * 128 + 2 * c) = pack_f16x2(acc[mt][nt][2], acc[mt][nt][3]);
            }
        }
    }
}

// ---------------- edge kernel: cp.async P prefetch overlapped with MMA ----------------
__global__ __launch_bounds__(256, 2)
void edge_mma_kernel(const float* __restrict__ ea,
                     const float* __restrict__ bfb,
                     const float* __restrict__ bsb,
                     const int*   __restrict__ esrc,
                     const int*   __restrict__ etgt,
                     int n_edges, int ntiles)
{
    extern __shared__ char smc[];
    unsigned sb = smem_u32(smc);
    int* s_src = (int*)(smc + EO_SRC);
    int* s_tgt = (int*)(smc + EO_TGT);
    float* s_bf = (float*)(smc + EO_BF);
    float* s_bs = (float*)(smc + EO_BS);
    unsigned* stage = (unsigned*)(smc + EO_STAGE);
    const unsigned* sp1 = (const unsigned*)(smc + EO_SP1);
    const unsigned* sp2 = (const unsigned*)(smc + EO_SP2);
    const int tid = threadIdx.x;
    const int w = tid >> 5;
    const int lane = tid & 31;
    const int mg = w >> 2;            // 0..1
    const int nq = w & 3;             // 0..3
    const int m0 = mg * 32;

    if (tid < DCH) { s_bf[tid] = bfb[tid]; s_bs[tid] = bsb[tid]; }

    // ---- B fragments straight from gmem (once) ----
    unsigned bh_fr[4][4][2], bl_fr[4][4][2];
    {
        const unsigned short* BH = g_Bh + 2 * 8192;
        const unsigned short* BL = g_Bl + 2 * 8192;
        int nrow = nq * 32 + (lane >> 2);
        int k0 = (lane & 3) * 2;
        #pragma unroll
        for (int kc = 0; kc < 4; kc++) {
            #pragma unroll
            for (int nt = 0; nt < 4; nt++) {
                int off = (nrow + nt * 8) * 64 + kc * 16 + k0;
                bh_fr[kc][nt][0] = *(const unsigned*)(BH + off);
                bh_fr[kc][nt][1] = *(const unsigned*)(BH + off + 8);
                bl_fr[kc][nt][0] = *(const unsigned*)(BL + off);
                bl_fr[kc][nt][1] = *(const unsigned*)(BL + off + 8);
            }
        }
    }

    const int rA0 = m0 + (lane & 15);
    const unsigned hiA = ((lane >> 4) & 1) << 4;
    const unsigned swA = (rA0 & 7) << 4;
    const unsigned aoff0 = sb + EO_AH + rA0 * 128;
    const unsigned aoff1 = aoff0 + 16 * 128;
    const int cq = lane & 3;
    const int li = lane & 7;
    const int egl = lane >> 3;

    __syncthreads();   // bias visible

    for (int t = blockIdx.x; t < ntiles; t += gridDim.x) {
        const int e0 = t * TILE_E;

        // ---- A tile fill + indices ----
        #pragma unroll
        for (int j = 0; j < 2; j++) {
            int idx = tid + j * 256;
            int e = idx >> 3;
            int cj = idx & 7;
            int ge = e0 + e;
            float4 v0, v1;
            if (ge < n_edges) {
                const float4* src = (const float4*)ea + (size_t)ge * 16 + cj * 2;
                v0 = src[0]; v1 = src[1];
            } else {
                v0 = make_float4(0.f, 0.f, 0.f, 0.f);
                v1 = v0;
            }
            unsigned H[4];
            H[0] = pack_f16x2(v0.x, v0.y);
            H[1] = pack_f16x2(v0.z, v0.w);
            H[2] = pack_f16x2(v1.x, v1.y);
            H[3] = pack_f16x2(v1.z, v1.w);
            unsigned dst = e * 128 + ((cj * 16) ^ ((e & 7) << 4));
            *(uint4*)(smc + EO_AH + dst) = make_uint4(H[0], H[1], H[2], H[3]);
        }
        if (tid < TILE_E) {
            int ge = e0 + tid;
            s_src[tid] = (ge < n_edges) ? esrc[ge] : 0;
            s_tgt[tid] = (ge < n_edges) ? etgt[ge] : 0;
        }
        __syncthreads();

        // ---- prefetch P rows for this tile (overlaps with MMA) ----
        #pragma unroll
        for (int j = 0; j < 8; j++) {
            int idx = tid + j * 256;           // 2048 chunks of 16B
            int e = idx >> 5;
            int sel = (idx >> 4) & 1;
            int ch = idx & 15;
            int node = sel ? s_tgt[e] : s_src[e];
            const unsigned short* Pg = sel ? g_P2h : g_P1h;
            const char* srcp = (const char*)(Pg + (size_t)node * 128) + ch * 16;
            unsigned dstp = sb + (sel ? EO_SP2 : EO_SP1) + e * 256 + ch * 16;
            CP_ASYNC16(dstp, srcp);
        }
        CP_COMMIT();

        // ---- mma mainloop ----
        float acc[2][4][4];
        #pragma unroll
        for (int mt = 0; mt < 2; mt++)
            #pragma unroll
            for (int nt = 0; nt < 4; nt++)
                #pragma unroll
                for (int p = 0; p < 4; p++) acc[mt][nt][p] = 0.0f;

        #pragma unroll
        for (int kc = 0; kc < 4; kc++) {
            unsigned ka = (unsigned)(kc * 32 + hiA) ^ swA;
            unsigned ah[4], ah2[4];
            LDSM4(ah,  aoff0 + ka);
            LDSM4(ah2, aoff1 + ka);
            #pragma unroll
            for (int nt = 0; nt < 4; nt++) {
                MMA16816(acc[0][nt], ah,  bh_fr[kc][nt][0], bh_fr[kc][nt][1]);
                MMA16816(acc[1][nt], ah2, bh_fr[kc][nt][0], bh_fr[kc][nt][1]);
                MMA16816(acc[0][nt], ah,  bl_fr[kc][nt][0], bl_fr[kc][nt][1]);
                MMA16816(acc[1][nt], ah2, bl_fr[kc][nt][0], bl_fr[kc][nt][1]);
            }
        }

        // ---- stage raw (g,v) as packed fp16 ----
        #pragma unroll
        for (int mt = 0; mt < 2; mt++) {
            int elo = m0 + mt * 16 + (lane >> 2);
            int ehi = elo + 8;
            #pragma unroll
            for (int nt = 0; nt < 4; nt++) {
                int c = nq * 16 + nt * 4 + cq;
                stage[elo * STGU + c] = pack_f16x2(acc[mt][nt][0], acc[mt][nt][1]);
                stage[ehi * STGU + c] = pack_f16x2(acc[mt][nt][2], acc[mt][nt][3]);
            }
        }
        CP_WAIT0();
        __syncthreads();

        // ---- per-edge epilogue: P reads from smem ----
        #pragma unroll
        for (int g2 = 0; g2 < 2; g2++) {
            int el = w * 8 + g2 * 4 + egl;
            int ge = e0 + el;
            int src = s_src[el];
            #pragma unroll
            for (int q = 0; q < 2; q++) {
                int cc = q * 32 + li * 4;
                uint4 st = *(const uint4*)(stage + el * STGU + cc);
                uint4 p1 = *(const uint4*)(sp1 + el * 64 + cc);
                uint4 p2 = *(const uint4*)(sp2 + el * 64 + cc);
                float4 bfv = *(const float4*)(s_bf + cc);
                float4 bsv = *(const float4*)(s_bs + cc);
                float2 s0 = unpack_h2(st.x), s1 = unpack_h2(st.y), s2 = unpack_h2(st.z), s3 = unpack_h2(st.w);
                float2 q10 = unpack_h2(p1.x), q11 = unpack_h2(p1.y), q12 = unpack_h2(p1.z), q13 = unpack_h2(p1.w);
                float2 q20 = unpack_h2(p2.x), q21 = unpack_h2(p2.y), q22 = unpack_h2(p2.z), q23 = unpack_h2(p2.w);
                float m0v = sigmoid_f(s0.x + q10.x + q20.x + bfv.x) * softplus_f(s0.y + q10.y + q20.y + bsv.x);
                float m1v = sigmoid_f(s1.x + q11.x + q21.x + bfv.y) * softplus_f(s1.y + q11.y + q21.y + bsv.y);
                float m2v = sigmoid_f(s2.x + q12.x + q22.x + bfv.z) * softplus_f(s2.y + q12.y + q22.y + bsv.z);
                float m3v = sigmoid_f(s3.x + q13.x + q23.x + bfv.w) * softplus_f(s3.y + q13.y + q23.y + bsv.w);
                if (ge < n_edges) {
                    float* dst = g_message + (size_t)src * 64 + cc;
                    asm volatile("red.global.add.v4.f32 [%0], {%1, %2, %3, %4};"
                                 :: "l"(dst), "f"(m0v), "f"(m1v), "f"(m2v), "f"(m3v)
                                 : "memory");
                }
            }
        }
        __syncthreads();   // protect smem before next tile's fill
    }
}

// ---------------- stats ----------------
__global__ __launch_bounds__(256)
void stats_kernel(int n4) {
    int t = blockIdx.x * blockDim.x + threadIdx.x;
    int stride = gridDim.x * blockDim.x;
    const float4* m4 = (const float4*)g_message;
    float4 s = make_float4(0.f, 0.f, 0.f, 0.f);
    float4 q = make_float4(0.f, 0.f, 0.f, 0.f);
    for (int i = t; i < n4; i += stride) {
        float4 v = m4[i];
        s.x += v.x; s.y += v.y; s.z += v.z; s.w += v.w;
        q.x += v.x * v.x; q.y += v.y * v.y; q.z += v.z * v.z; q.w += v.w * v.w;
    }
    __shared__ float4 ss[256];
    __shared__ float4 qq[256];
    ss[threadIdx.x] = s;
    qq[threadIdx.x] = q;
    __syncthreads();
    #pragma unroll
    for (int off = 128; off >= 16; off >>= 1) {
        if (threadIdx.x < off) {
            float4 a = ss[threadIdx.x + off], b = qq[threadIdx.x + off];
            float4 sa = ss[threadIdx.x], qa = qq[threadIdx.x];
            sa.x += a.x; sa.y += a.y; sa.z += a.z; sa.w += a.w;
            qa.x += b.x; qa.y += b.y; qa.z += b.z; qa.w += b.w;
            ss[threadIdx.x] = sa;
            qq[threadIdx.x] = qa;
        }
        __syncthreads();
    }
    if (threadIdx.x < 16) {
        int c = threadIdx.x * 4;
        float4 sa = ss[threadIdx.x], qa = qq[threadIdx.x];
        atomicAdd(&g_sum[c + 0], sa.x); atomicAdd(&g_sum[c + 1], sa.y);
        atomicAdd(&g_sum[c + 2], sa.z); atomicAdd(&g_sum[c + 3], sa.w);
        atomicAdd(&g_sumsq[c + 0], qa.x); atomicAdd(&g_sumsq[c + 1], qa.y);
        atomicAdd(&g_sumsq[c + 2], qa.z); atomicAdd(&g_sumsq[c + 3], qa.w);
    }
}

// ---------------- final ----------------
__global__ __launch_bounds__(256)
void final_kernel(const float* __restrict__ x,
                  const float* __restrict__ gamma,
                  const float* __restrict__ beta,
                  float* __restrict__ out,
                  int n4, float inv_n)
{
    int i = blockIdx.x * blockDim.x + threadIdx.x;
    if (i >= n4) return;
    int c = (i & 15) * 4;
    float4 mm = ((const float4*)g_message)[i];
    float4 xx = ((const float4*)x)[i];
    float4 gm = ((const float4*)gamma)[i & 15];
    float4 bt = ((const float4*)beta)[i & 15];
    float mv[4] = {mm.x, mm.y, mm.z, mm.w};
    float xv[4] = {xx.x, xx.y, xx.z, xx.w};
    float gv[4] = {gm.x, gm.y, gm.z, gm.w};
    float bv[4] = {bt.x, bt.y, bt.z, bt.w};
    float ov[4];
    #pragma unroll
    for (int j = 0; j < 4; j++) {
        float mean = g_sum[c + j] * inv_n;
        float var  = g_sumsq[c + j] * inv_n - mean * mean;
        float inv_std = rsqrtf(var + 1e-5f);
        float mn = (mv[j] - mean) * inv_std * gv[j] + bv[j];
        float t = xv[j] + mn;
        ov[j] = fmaxf(t, 0.0f) + log1pf(expf(-fabsf(t)));
    }
    ((float4*)out)[i] = make_float4(ov[0], ov[1], ov[2], ov[3]);
}

extern "C" void kernel_launch(void* const* d_in, const int* in_sizes, int n_in,
                              void* d_out, int out_size)
{
    const float* x     = (const float*)d_in[0];
    const float* ea    = (const float*)d_in[1];
    const float* Wf    = (const float*)d_in[2];
    const float* bf    = (const float*)d_in[3];
    const float* Ws    = (const float*)d_in[4];
    const float* bs    = (const float*)d_in[5];
    const float* gamma = (const float*)d_in[6];
    const float* beta  = (const float*)d_in[7];
    const int*   esrc  = (const int*)d_in[8];
    const int*   etgt  = (const int*)d_in[9];
    float* out = (float*)d_out;

    int n_nodes = in_sizes[0] / DCH;
    int n_edges = in_sizes[8];
    int total   = n_nodes * DCH;
    int total4  = total / 4;
    int etiles  = (n_edges + TILE_E - 1) / TILE_E;
    int ntiles  = (n_nodes + 127) / 128;

    static bool attr_set = false;
    if (!attr_set) {
        cudaFuncSetAttribute(edge_mma_kernel, cudaFuncAttributeMaxDynamicSharedMemorySize, EDGE_SMEM_BYTES);
        cudaFuncSetAttribute(node_mma_kernel, cudaFuncAttributeMaxDynamicSharedMemorySize, NODE_SMEM_BYTES);
        attr_set = true;
    }

    {   // 1
        int grid = (total4 + 255) / 256;
        if (grid > 1024) grid = 1024;
        zero_kernel<<<grid, 256>>>(total4);
    }
    prep_B_kernel<<<96, 256>>>(Wf, Ws);                                      // 2
    {   // 3
        dim3 grid(148, 2);
        node_mma_kernel<<<grid, 256, NODE_SMEM_BYTES>>>(x, n_nodes, ntiles);
    }
    {   // 4  <- ncu slot
        int grid = 296;
        if (grid > etiles) grid = etiles;
        edge_mma_kernel<<<grid, 256, EDGE_SMEM_BYTES>>>(ea, bf, bs, esrc, etgt, n_edges, etiles);
    }
    stats_kernel<<<512, 256>>>(total4);                                      // 5
    {   // 6
        int grid = (total4 + 255) / 256;
        final_kernel<<<grid, 256>>>(x, gamma, beta, out, total4, 1.0f / (float)n_nodes);
    }
}

// round 13
// speedup vs baseline: 1.3837x; 1.0229x over previous
#include <cuda_runtime.h>
#include <cuda_fp16.h>
#include <math.h>

#define DCH    64
#define FAN    192
#define TILE_E 64
#define MAX_NODES 50176

__device__ float g_message[MAX_NODES * DCH];
__device__ unsigned short g_P1h[MAX_NODES * 128];
__device__ unsigned short g_P2h[MAX_NODES * 128];
__device__ float g_sum[DCH];
__device__ float g_sumsq[DCH];
__device__ unsigned short g_Bh[3 * 128 * 64];
__device__ unsigned short g_Bl[3 * 128 * 64];

// ---------------- edge kernel smem (bytes) ----------------
#define EO_SRC   0                 // 256 B
#define EO_TGT   256
#define EO_AH    1024              // 64*128 = 8192 B
#define EO_STAGE 9216              // 64 rows x 68 u32 = 17408 B
#define STGU     68
#define EO_SP1   26624             // 64 edges x 256 B = 16384
#define EO_SP2   43008             // 16384
#define EDGE_SMEM_BYTES 59392

// ---------------- node kernel smem ----------------
#define NO_AH    0
#define NO_AL    16384
#define NO_BH    32768
#define NO_BL    49152
#define NODE_SMEM_BYTES 65536

// ---------------- helpers ----------------
__device__ __forceinline__ unsigned smem_u32(const void* p) {
    unsigned a;
    asm("{ .reg .u64 t; cvta.to.shared.u64 t, %1; cvt.u32.u64 %0, t; }" : "=r"(a) : "l"(p));
    return a;
}
__device__ __forceinline__ unsigned pack_f16x2(float lo, float hi) {
    unsigned r;
    asm("cvt.rn.f16x2.f32 %0, %1, %2;" : "=r"(r) : "f"(hi), "f"(lo));
    return r;
}
__device__ __forceinline__ unsigned hadd2u(unsigned a, unsigned b) {
    unsigned d;
    asm("add.rn.f16x2 %0, %1, %2;" : "=r"(d) : "r"(a), "r"(b));
    return d;
}
__device__ __forceinline__ float2 unpack_h2(unsigned u) {
    __half2 h = *reinterpret_cast<__half2*>(&u);
    return __half22float2(h);
}
__device__ __forceinline__ float ex2a(float x) { float r; asm("ex2.approx.f32 %0, %1;" : "=f"(r) : "f"(x)); return r; }
__device__ __forceinline__ float lg2a(float x) { float r; asm("lg2.approx.f32 %0, %1;" : "=f"(r) : "f"(x)); return r; }
__device__ __forceinline__ float rcpa(float x) { float r; asm("rcp.approx.f32 %0, %1;" : "=f"(r) : "f"(x)); return r; }
__device__ __forceinline__ float sigmoid_f(float g) {
    return rcpa(1.0f + ex2a(-1.44269504f * g));
}
__device__ __forceinline__ float softplus_f(float v) {
    float u = ex2a(-1.44269504f * fabsf(v));
    return fmaxf(v, 0.0f) + 0.69314718f * lg2a(1.0f + u);
}

#define LDSM4(R, A) \
    asm volatile("ldmatrix.sync.aligned.m8n8.x4.shared.b16 {%0,%1,%2,%3}, [%4];" \
        : "=r"((R)[0]), "=r"((R)[1]), "=r"((R)[2]), "=r"((R)[3]) : "r"(A))
#define LDSM2(R0, R1, A) \
    asm volatile("ldmatrix.sync.aligned.m8n8.x2.shared.b16 {%0,%1}, [%2];" \
        : "=r"(R0), "=r"(R1) : "r"(A))
#define MMA16816(D, A, B0, B1) \
    asm volatile("mma.sync.aligned.m16n8k16.row.col.f32.f16.f16.f32 " \
        "{%0,%1,%2,%3}, {%4,%5,%6,%7}, {%8,%9}, {%0,%1,%2,%3};" \
        : "+f"((D)[0]), "+f"((D)[1]), "+f"((D)[2]), "+f"((D)[3]) \
        : "r"((A)[0]), "r"((A)[1]), "r"((A)[2]), "r"((A)[3]), "r"(B0), "r"(B1))
#define CP_ASYNC16(dst, src) \
    asm volatile("cp.async.cg.shared.global [%0], [%1], 16;" :: "r"(dst), "l"(src))
#define CP_COMMIT() asm volatile("cp.async.commit_group;" ::: "memory")
#define CP_WAIT0()  asm volatile("cp.async.wait_group 0;" ::: "memory")

// ---------------- prep: all 3 W slices -> fp16 hi/lo ----------------
__global__ void prep_B_kernel(const float* __restrict__ Wf, const float* __restrict__ Ws) {
    int idx = blockIdx.x * 256 + threadIdx.x;   // 24576
    int s = idx >> 13;
    int r = idx & 8191;
    int n = r >> 6;
    int k = r & 63;
    int d = n >> 1;
    const float* w = (n & 1) ? Ws : Wf;
    float v = w[d * FAN + s * 64 + k];
    __half h = __float2half_rn(v);
    __half l = __float2half_rn(v - __half2float(h));
    g_Bh[idx] = __half_as_ushort(h);
    g_Bl[idx] = __half_as_ushort(l);
}

// ---------------- zero ----------------
__global__ void zero_kernel(int total4) {
    int i = blockIdx.x * blockDim.x + threadIdx.x;
    int stride = gridDim.x * blockDim.x;
    float4* m4 = (float4*)g_message;
    for (int j = i; j < total4; j += stride) m4[j] = make_float4(0.f, 0.f, 0.f, 0.f);
    if (i < DCH) { g_sum[i] = 0.0f; g_sumsq[i] = 0.0f; }
}

// ---------------- node projections on tensor cores -> fp16 P ----------------
__global__ __launch_bounds__(256, 2)
void node_mma_kernel(const float* __restrict__ x, int n_nodes, int ntiles)
{
    extern __shared__ char smc[];
    unsigned sb = smem_u32(smc);
    const int tid = threadIdx.x;
    const int wsel = blockIdx.y;
    unsigned short* P = wsel ? g_P2h : g_P1h;

    {
        const uint4* bh = (const uint4*)g_Bh + wsel * 1024;
        const uint4* bl = (const uint4*)g_Bl + wsel * 1024;
        #pragma unroll
        for (int j = 0; j < 4; j++) {
            int idx = tid + j * 256;
            int n = idx >> 3;
            int cj = idx & 7;
            unsigned dst = n * 128 + ((cj * 16) ^ ((n & 7) << 4));
            *(uint4*)(smc + NO_BH + dst) = bh[idx];
            *(uint4*)(smc + NO_BL + dst) = bl[idx];
        }
    }

    const int w = tid >> 5;
    const int lane = tid & 31;
    const int m0 = (w & 3) * 32;
    const int nn0 = (w >> 2) * 64;
    const int rA0 = m0 + (lane & 15);
    const unsigned hiA = ((lane >> 4) & 1) << 4;
    const unsigned swA = (rA0 & 7) << 4;
    const int rB = nn0 + (lane & 7);
    const unsigned hiB = ((lane >> 3) & 1) << 4;
    const unsigned swB = (lane & 7) << 4;
    const unsigned boff = sb + NO_BH + rB * 128;
    const int cq = lane & 3;
    const int cbase = (w >> 2) * 32;

    for (int t = blockIdx.x; t < ntiles; t += 148) {
        int n0 = t * 128;
        __syncthreads();
        #pragma unroll
        for (int j = 0; j < 4; j++) {
            int idx = tid + j * 256;
            int e = idx >> 3;
            int cj = idx & 7;
            float4 v0, v1;
            if (n0 + e < n_nodes) {
                const float4* src = (const float4*)x + (size_t)(n0 + e) * 16 + cj * 2;
                v0 = src[0]; v1 = src[1];
            } else {
                v0 = make_float4(0.f, 0.f, 0.f, 0.f);
                v1 = v0;
            }
            float vv[8] = {v0.x, v0.y, v0.z, v0.w, v1.x, v1.y, v1.z, v1.w};
            unsigned H[4], L[4];
            #pragma unroll
            for (int p = 0; p < 4; p++) {
                __half h0 = __float2half_rn(vv[2 * p]);
                __half h1 = __float2half_rn(vv[2 * p + 1]);
                __half l0 = __float2half_rn(vv[2 * p] - __half2float(h0));
                __half l1 = __float2half_rn(vv[2 * p + 1] - __half2float(h1));
                H[p] = (unsigned)__half_as_ushort(h0) | ((unsigned)__half_as_ushort(h1) << 16);
                L[p] = (unsigned)__half_as_ushort(l0) | ((unsigned)__half_as_ushort(l1) << 16);
            }
            unsigned dst = e * 128 + ((cj * 16) ^ ((e & 7) << 4));
            *(uint4*)(smc + NO_AH + dst) = make_uint4(H[0], H[1], H[2], H[3]);
            *(uint4*)(smc + NO_AL + dst) = make_uint4(L[0], L[1], L[2], L[3]);
        }
        __syncthreads();

        float acc[2][8][4];
        #pragma unroll
        for (int mt = 0; mt < 2; mt++)
            #pragma unroll
            for (int nt = 0; nt < 8; nt++)
                #pragma unroll
                for (int p = 0; p < 4; p++) acc[mt][nt][p] = 0.0f;

        const unsigned aoff0 = sb + NO_AH + rA0 * 128;
        const unsigned aoff1 = aoff0 + 16 * 128;
        #pragma unroll
        for (int kc = 0; kc < 4; kc++) {
            unsigned ka = (unsigned)(kc * 32 + hiA) ^ swA;
            unsigned ah[4], ah2[4], al[4], al2[4];
            LDSM4(ah,  aoff0 + ka);
            LDSM4(ah2, aoff1 + ka);
            LDSM4(al,  aoff0 + ka + 16384);
            LDSM4(al2, aoff1 + ka + 16384);
            unsigned kb = (unsigned)(kc * 32 + hiB) ^ swB;
            #pragma unroll
            for (int nt = 0; nt < 8; nt++) {
                unsigned ba = boff + nt * 8 * 128 + kb;
                unsigned bh0, bh1, bl0, bl1;
                LDSM2(bh0, bh1, ba);
                LDSM2(bl0, bl1, ba + 16384);
                MMA16816(acc[0][nt], ah,  bh0, bh1);
                MMA16816(acc[1][nt], ah2, bh0, bh1);
                MMA16816(acc[0][nt], ah,  bl0, bl1);
                MMA16816(acc[1][nt], ah2, bl0, bl1);
                MMA16816(acc[0][nt], al,  bh0, bh1);
                MMA16816(acc[1][nt], al2, bh0, bh1);
            }
        }

        #pragma unroll
        for (int mt = 0; mt < 2; mt++) {
            int elo = m0 + mt * 16 + (lane >> 2);
            int ehi = elo + 8;
            #pragma unroll
            for (int nt = 0; nt < 8; nt++) {
                int c = cbase + nt * 4 + cq;
                if (n0 + elo < n_nodes)
                    *(unsigned*)(P + (size_t)(n0 + elo) * 128 + 2 * c) = pack_f16x2(acc[mt][nt][0], acc[mt][nt][1]);
                if (n0 + ehi < n_nodes)
                    *(unsigned*)(P + (size_t)(n0 + ehi) * 128 + 2 * c) = pack_f16x2(acc[mt][nt][2], acc[mt][nt][3]);
            }
        }
    }
}

// ---------------- edge kernel ----------------
__global__ __launch_bounds__(256, 2)
void edge_mma_kernel(const float* __restrict__ ea,
                     const float* __restrict__ bfb,
                     const float* __restrict__ bsb,
                     const int*   __restrict__ esrc,
                     const int*   __restrict__ etgt,
                     int n_edges, int ntiles)
{
    extern __shared__ char smc[];
    unsigned sb = smem_u32(smc);
    int* s_src = (int*)(smc + EO_SRC);
    int* s_tgt = (int*)(smc + EO_TGT);
    unsigned* stage = (unsigned*)(smc + EO_STAGE);
    const unsigned* sp1 = (const unsigned*)(smc + EO_SP1);
    const unsigned* sp2 = (const unsigned*)(smc + EO_SP2);
    const int tid = threadIdx.x;
    const int w = tid >> 5;
    const int lane = tid & 31;
    const int mg = w >> 2;            // 0..1
    const int nq = w & 3;             // 0..3
    const int m0 = mg * 32;
    const int cq = lane & 3;

    // ---- bias into registers (pre-loaded into MMA accumulators) ----
    float bfv[4], bsv[4];
    {
        int c0 = nq * 16 + cq;
        #pragma unroll
        for (int nt = 0; nt < 4; nt++) {
            bfv[nt] = bfb[c0 + nt * 4];
            bsv[nt] = bsb[c0 + nt * 4];
        }
    }

    // ---- B fragments straight from gmem (once) ----
    unsigned bh_fr[4][4][2], bl_fr[4][4][2];
    {
        const unsigned short* BH = g_Bh + 2 * 8192;
        const unsigned short* BL = g_Bl + 2 * 8192;
        int nrow = nq * 32 + (lane >> 2);
        int k0 = (lane & 3) * 2;
        #pragma unroll
        for (int kc = 0; kc < 4; kc++) {
            #pragma unroll
            for (int nt = 0; nt < 4; nt++) {
                int off = (nrow + nt * 8) * 64 + kc * 16 + k0;
                bh_fr[kc][nt][0] = *(const unsigned*)(BH + off);
                bh_fr[kc][nt][1] = *(const unsigned*)(BH + off + 8);
                bl_fr[kc][nt][0] = *(const unsigned*)(BL + off);
                bl_fr[kc][nt][1] = *(const unsigned*)(BL + off + 8);
            }
        }
    }

    const int rA0 = m0 + (lane & 15);
    const unsigned hiA = ((lane >> 4) & 1) << 4;
    const unsigned swA = (rA0 & 7) << 4;
    const unsigned aoff0 = sb + EO_AH + rA0 * 128;
    const unsigned aoff1 = aoff0 + 16 * 128;
    const int li = lane & 7;
    const int egl = lane >> 3;

    // strength-reduced cp.async constants
    const int cp_e0 = tid >> 5;               // +8 per j
    const int cp_sel = (tid >> 4) & 1;
    const int cp_ch16 = (tid & 15) * 16;
    const unsigned short* cp_P = cp_sel ? g_P2h : g_P1h;
    const int* cp_idx = cp_sel ? s_tgt : s_src;
    const unsigned cp_dst0 = sb + (cp_sel ? EO_SP2 : EO_SP1) + cp_e0 * 256 + cp_ch16;

    __syncthreads();

    for (int t = blockIdx.x; t < ntiles; t += gridDim.x) {
        const int e0 = t * TILE_E;

        // ---- A tile fill + indices ----
        #pragma unroll
        for (int j = 0; j < 2; j++) {
            int idx = tid + j * 256;
            int e = idx >> 3;
            int cj = idx & 7;
            int ge = e0 + e;
            float4 v0, v1;
            if (ge < n_edges) {
                const float4* src = (const float4*)ea + (size_t)ge * 16 + cj * 2;
                v0 = src[0]; v1 = src[1];
            } else {
                v0 = make_float4(0.f, 0.f, 0.f, 0.f);
                v1 = v0;
            }
            unsigned H[4];
            H[0] = pack_f16x2(v0.x, v0.y);
            H[1] = pack_f16x2(v0.z, v0.w);
            H[2] = pack_f16x2(v1.x, v1.y);
            H[3] = pack_f16x2(v1.z, v1.w);
            unsigned dst = e * 128 + ((cj * 16) ^ ((e & 7) << 4));
            *(uint4*)(smc + EO_AH + dst) = make_uint4(H[0], H[1], H[2], H[3]);
        }
        if (tid < TILE_E) {
            int ge = e0 + tid;
            s_src[tid] = (ge < n_edges) ? esrc[ge] : 0;
            s_tgt[tid] = (ge < n_edges) ? etgt[ge] : 0;
        }
        __syncthreads();

        // ---- prefetch P rows (overlaps with MMA) ----
        #pragma unroll
        for (int j = 0; j < 8; j++) {
            int node = cp_idx[cp_e0 + j * 8];
            const char* srcp = (const char*)(cp_P + (size_t)node * 128) + cp_ch16;
            CP_ASYNC16(cp_dst0 + j * 2048, srcp);
        }
        CP_COMMIT();

        // ---- mma mainloop (acc pre-loaded with bias) ----
        float acc[2][4][4];
        #pragma unroll
        for (int mt = 0; mt < 2; mt++)
            #pragma unroll
            for (int nt = 0; nt < 4; nt++) {
                acc[mt][nt][0] = bfv[nt];
                acc[mt][nt][1] = bsv[nt];
                acc[mt][nt][2] = bfv[nt];
                acc[mt][nt][3] = bsv[nt];
            }

        #pragma unroll
        for (int kc = 0; kc < 4; kc++) {
            unsigned ka = (unsigned)(kc * 32 + hiA) ^ swA;
            unsigned ah[4], ah2[4];
            LDSM4(ah,  aoff0 + ka);
            LDSM4(ah2, aoff1 + ka);
            #pragma unroll
            for (int nt = 0; nt < 4; nt++) {
                MMA16816(acc[0][nt], ah,  bh_fr[kc][nt][0], bh_fr[kc][nt][1]);
                MMA16816(acc[1][nt], ah2, bh_fr[kc][nt][0], bh_fr[kc][nt][1]);
                MMA16816(acc[0][nt], ah,  bl_fr[kc][nt][0], bl_fr[kc][nt][1]);
                MMA16816(acc[1][nt], ah2, bl_fr[kc][nt][0], bl_fr[kc][nt][1]);
            }
        }

        // ---- stage raw (g,v)+bias as packed fp16 ----
        #pragma unroll
        for (int mt = 0; mt < 2; mt++) {
            int elo = m0 + mt * 16 + (lane >> 2);
            int ehi = elo + 8;
            #pragma unroll
            for (int nt = 0; nt < 4; nt++) {
                int c = nq * 16 + nt * 4 + cq;
                stage[elo * STGU + c] = pack_f16x2(acc[mt][nt][0], acc[mt][nt][1]);
                stage[ehi * STGU + c] = pack_f16x2(acc[mt][nt][2], acc[mt][nt][3]);
            }
        }
        CP_WAIT0();
        __syncthreads();

        // ---- per-edge epilogue: half2 sums, activations, scatter ----
        #pragma unroll
        for (int g2 = 0; g2 < 2; g2++) {
            int el = w * 8 + g2 * 4 + egl;
            int ge = e0 + el;
            int src = s_src[el];
            #pragma unroll
            for (int q = 0; q < 2; q++) {
                int cc = q * 32 + li * 4;
                uint4 st = *(const uint4*)(stage + el * STGU + cc);
                uint4 p1 = *(const uint4*)(sp1 + el * 64 + cc);
                uint4 p2 = *(const uint4*)(sp2 + el * 64 + cc);
                unsigned u0 = hadd2u(hadd2u(st.x, p1.x), p2.x);
                unsigned u1 = hadd2u(hadd2u(st.y, p1.y), p2.y);
                unsigned u2 = hadd2u(hadd2u(st.z, p1.z), p2.z);
                unsigned u3 = hadd2u(hadd2u(st.w, p1.w), p2.w);
                float2 f0 = unpack_h2(u0), f1 = unpack_h2(u1), f2 = unpack_h2(u2), f3 = unpack_h2(u3);
                float m0v = sigmoid_f(f0.x) * softplus_f(f0.y);
                float m1v = sigmoid_f(f1.x) * softplus_f(f1.y);
                float m2v = sigmoid_f(f2.x) * softplus_f(f2.y);
                float m3v = sigmoid_f(f3.x) * softplus_f(f3.y);
                if (ge < n_edges) {
                    float* dst = g_message + (size_t)src * 64 + cc;
                    asm volatile("red.global.add.v4.f32 [%0], {%1, %2, %3, %4};"
                                 :: "l"(dst), "f"(m0v), "f"(m1v), "f"(m2v), "f"(m3v)
                                 : "memory");
                }
            }
        }
        __syncthreads();
    }
}

// ---------------- stats ----------------
__global__ __launch_bounds__(256)
void stats_kernel(int n4) {
    int t = blockIdx.x * blockDim.x + threadIdx.x;
    int stride = gridDim.x * blockDim.x;
    const float4* m4 = (const float4*)g_message;
    float4 s = make_float4(0.f, 0.f, 0.f, 0.f);
    float4 q = make_float4(0.f, 0.f, 0.f, 0.f);
    for (int i = t; i < n4; i += stride) {
        float4 v = m4[i];
        s.x += v.x; s.y += v.y; s.z += v.z; s.w += v.w;
        q.x += v.x * v.x; q.y += v.y * v.y; q.z += v.z * v.z; q.w += v.w * v.w;
    }
    __shared__ float4 ss[256];
    __shared__ float4 qq[256];
    ss[threadIdx.x] = s;
    qq[threadIdx.x] = q;
    __syncthreads();
    #pragma unroll
    for (int off = 128; off >= 16; off >>= 1) {
        if (threadIdx.x < off) {
            float4 a = ss[threadIdx.x + off], b = qq[threadIdx.x + off];
            float4 sa = ss[threadIdx.x], qa = qq[threadIdx.x];
            sa.x += a.x; sa.y += a.y; sa.z += a.z; sa.w += a.w;
            qa.x += b.x; qa.y += b.y; qa.z += b.z; qa.w += b.w;
            ss[threadIdx.x] = sa;
            qq[threadIdx.x] = qa;
        }
        __syncthreads();
    }
    if (threadIdx.x < 16) {
        int c = threadIdx.x * 4;
        float4 sa = ss[threadIdx.x], qa = qq[threadIdx.x];
        atomicAdd(&g_sum[c + 0], sa.x); atomicAdd(&g_sum[c + 1], sa.y);
        atomicAdd(&g_sum[c + 2], sa.z); atomicAdd(&g_sum[c + 3], sa.w);
        atomicAdd(&g_sumsq[c + 0], qa.x); atomicAdd(&g_sumsq[c + 1], qa.y);
        atomicAdd(&g_sumsq[c + 2], qa.z); atomicAdd(&g_sumsq[c + 3], qa.w);
    }
}

// ---------------- final ----------------
__global__ __launch_bounds__(256)
void final_kernel(const float* __restrict__ x,
                  const float* __restrict__ gamma,
                  const float* __restrict__ beta,
                  float* __restrict__ out,
                  int n4, float inv_n)
{
    int i = blockIdx.x * blockDim.x + threadIdx.x;
    if (i >= n4) return;
    int c = (i & 15) * 4;
    float4 mm = ((const float4*)g_message)[i];
    float4 xx = ((const float4*)x)[i];
    float4 gm = ((const float4*)gamma)[i & 15];
    float4 bt = ((const float4*)beta)[i & 15];
    float mv[4] = {mm.x, mm.y, mm.z, mm.w};
    float xv[4] = {xx.x, xx.y, xx.z, xx.w};
    float gv[4] = {gm.x, gm.y, gm.z, gm.w};
    float bv[4] = {bt.x, bt.y, bt.z, bt.w};
    float ov[4];
    #pragma unroll
    for (int j = 0; j < 4; j++) {
        float mean = g_sum[c + j] * inv_n;
        float var  = g_sumsq[c + j] * inv_n - mean * mean;
        float inv_std = rsqrtf(var + 1e-5f);
        float mn = (mv[j] - mean) * inv_std * gv[j] + bv[j];
        float t = xv[j] + mn;
        ov[j] = fmaxf(t, 0.0f) + log1pf(expf(-fabsf(t)));
    }
    ((float4*)out)[i] = make_float4(ov[0], ov[1], ov[2], ov[3]);
}

extern "C" void kernel_launch(void* const* d_in, const int* in_sizes, int n_in,
                              void* d_out, int out_size)
{
    const float* x     = (const float*)d_in[0];
    const float* ea    = (const float*)d_in[1];
    const float* Wf    = (const float*)d_in[2];
    const float* bf    = (const float*)d_in[3];
    const float* Ws    = (const float*)d_in[4];
    const float* bs    = (const float*)d_in[5];
    const float* gamma = (const float*)d_in[6];
    const float* beta  = (const float*)d_in[7];
    const int*   esrc  = (const int*)d_in[8];
    const int*   etgt  = (const int*)d_in[9];
    float* out = (float*)d_out;

    int n_nodes = in_sizes[0] / DCH;
    int n_edges = in_sizes[8];
    int total   = n_nodes * DCH;
    int total4  = total / 4;
    int etiles  = (n_edges + TILE_E - 1) / TILE_E;
    int ntiles  = (n_nodes + 127) / 128;

    static bool attr_set = false;
    if (!attr_set) {
        cudaFuncSetAttribute(edge_mma_kernel, cudaFuncAttributeMaxDynamicSharedMemorySize, EDGE_SMEM_BYTES);
        cudaFuncSetAttribute(node_mma_kernel, cudaFuncAttributeMaxDynamicSharedMemorySize, NODE_SMEM_BYTES);
        attr_set = true;
    }

    {   // 1
        int grid = (total4 + 255) / 256;
        if (grid > 1024) grid = 1024;
        zero_kernel<<<grid, 256>>>(total4);
    }
    prep_B_kernel<<<96, 256>>>(Wf, Ws);                                      // 2
    {   // 3
        dim3 grid(148, 2);
        node_mma_kernel<<<grid, 256, NODE_SMEM_BYTES>>>(x, n_nodes, ntiles);
    }
    {   // 4  <- ncu slot
        int grid = 296;
        if (grid > etiles) grid = etiles;
        edge_mma_kernel<<<grid, 256, EDGE_SMEM_BYTES>>>(ea, bf, bs, esrc, etgt, n_edges, etiles);
    }
    stats_kernel<<<512, 256>>>(total4);                                      // 5
    {   // 6
        int grid = (total4 + 255) / 256;
        final_kernel<<<grid, 256>>>(x, gamma, beta, out, total4, 1.0f / (float)n_nodes);
    }
}

// round 14
// speedup vs baseline: 1.5428x; 1.1149x over previous
#include <cuda_runtime.h>
#include <cuda_fp16.h>
#include <math.h>

#define DCH    64
#define FAN    192
#define TILE_E 64
#define MAX_NODES 50176

__device__ float g_message[MAX_NODES * DCH];
__device__ unsigned short g_P1h[MAX_NODES * 128];
__device__ unsigned short g_P2h[MAX_NODES * 128];
__device__ float g_sum[DCH];
__device__ float g_sumsq[DCH];
__device__ unsigned short g_Bh[3 * 128 * 64];
__device__ unsigned short g_Bl[3 * 128 * 64];

// ---------------- edge kernel smem (bytes) ----------------
#define EO_SRC   0                 // 2 bufs x 64 ints = 512
#define EO_TGT   512               // 512
#define EO_ARAW  1024              // 2 x 16384 = 32768
#define EO_AH    33792             // 8192
#define EO_STAGE 41984             // 64 x 68 u32 = 17408
#define STGU     68
#define EO_SP1   59392             // 16384
#define EO_SP2   75776             // 16384
#define EDGE_SMEM_BYTES 92160

// ---------------- node kernel smem ----------------
#define NO_AH    0
#define NO_AL    16384
#define NO_BH    32768
#define NO_BL    49152
#define NODE_SMEM_BYTES 65536

// ---------------- helpers ----------------
__device__ __forceinline__ unsigned smem_u32(const void* p) {
    unsigned a;
    asm("{ .reg .u64 t; cvta.to.shared.u64 t, %1; cvt.u32.u64 %0, t; }" : "=r"(a) : "l"(p));
    return a;
}
__device__ __forceinline__ unsigned pack_f16x2(float lo, float hi) {
    unsigned r;
    asm("cvt.rn.f16x2.f32 %0, %1, %2;" : "=r"(r) : "f"(hi), "f"(lo));
    return r;
}
__device__ __forceinline__ unsigned hadd2u(unsigned a, unsigned b) {
    unsigned d;
    asm("add.rn.f16x2 %0, %1, %2;" : "=r"(d) : "r"(a), "r"(b));
    return d;
}
__device__ __forceinline__ float2 unpack_h2(unsigned u) {
    __half2 h = *reinterpret_cast<__half2*>(&u);
    return __half22float2(h);
}
__device__ __forceinline__ float ex2a(float x) { float r; asm("ex2.approx.f32 %0, %1;" : "=f"(r) : "f"(x)); return r; }
__device__ __forceinline__ float lg2a(float x) { float r; asm("lg2.approx.f32 %0, %1;" : "=f"(r) : "f"(x)); return r; }
__device__ __forceinline__ float sigmoid_f(float g) {
    float t;
    asm("tanh.approx.f32 %0, %1;" : "=f"(t) : "f"(g * 0.5f));
    return fmaf(t, 0.5f, 0.5f);
}
__device__ __forceinline__ float softplus_f(float v) {
    float u = ex2a(-1.44269504f * fabsf(v));
    return fmaxf(v, 0.0f) + 0.69314718f * lg2a(1.0f + u);
}

#define LDSM4(R, A) \
    asm volatile("ldmatrix.sync.aligned.m8n8.x4.shared.b16 {%0,%1,%2,%3}, [%4];" \
        : "=r"((R)[0]), "=r"((R)[1]), "=r"((R)[2]), "=r"((R)[3]) : "r"(A))
#define LDSM2(R0, R1, A) \
    asm volatile("ldmatrix.sync.aligned.m8n8.x2.shared.b16 {%0,%1}, [%2];" \
        : "=r"(R0), "=r"(R1) : "r"(A))
#define MMA16816(D, A, B0, B1) \
    asm volatile("mma.sync.aligned.m16n8k16.row.col.f32.f16.f16.f32 " \
        "{%0,%1,%2,%3}, {%4,%5,%6,%7}, {%8,%9}, {%0,%1,%2,%3};" \
        : "+f"((D)[0]), "+f"((D)[1]), "+f"((D)[2]), "+f"((D)[3]) \
        : "r"((A)[0]), "r"((A)[1]), "r"((A)[2]), "r"((A)[3]), "r"(B0), "r"(B1))
#define CP_ASYNC16(dst, src) \
    asm volatile("cp.async.cg.shared.global [%0], [%1], 16;" :: "r"(dst), "l"(src))
#define CP_COMMIT() asm volatile("cp.async.commit_group;" ::: "memory")
#define CP_WAIT0()  asm volatile("cp.async.wait_group 0;" ::: "memory")

// ---------------- prep: all 3 W slices -> fp16 hi/lo ----------------
__global__ void prep_B_kernel(const float* __restrict__ Wf, const float* __restrict__ Ws) {
    int idx = blockIdx.x * 256 + threadIdx.x;   // 24576
    int s = idx >> 13;
    int r = idx & 8191;
    int n = r >> 6;
    int k = r & 63;
    int d = n >> 1;
    const float* w = (n & 1) ? Ws : Wf;
    float v = w[d * FAN + s * 64 + k];
    __half h = __float2half_rn(v);
    __half l = __float2half_rn(v - __half2float(h));
    g_Bh[idx] = __half_as_ushort(h);
    g_Bl[idx] = __half_as_ushort(l);
}

// ---------------- zero ----------------
__global__ void zero_kernel(int total4) {
    int i = blockIdx.x * blockDim.x + threadIdx.x;
    int stride = gridDim.x * blockDim.x;
    float4* m4 = (float4*)g_message;
    for (int j = i; j < total4; j += stride) m4[j] = make_float4(0.f, 0.f, 0.f, 0.f);
    if (i < DCH) { g_sum[i] = 0.0f; g_sumsq[i] = 0.0f; }
}

// ---------------- node projections on tensor cores -> fp16 P ----------------
__global__ __launch_bounds__(256, 2)
void node_mma_kernel(const float* __restrict__ x, int n_nodes, int ntiles)
{
    extern __shared__ char smc[];
    unsigned sb = smem_u32(smc);
    const int tid = threadIdx.x;
    const int wsel = blockIdx.y;
    unsigned short* P = wsel ? g_P2h : g_P1h;

    {
        const uint4* bh = (const uint4*)g_Bh + wsel * 1024;
        const uint4* bl = (const uint4*)g_Bl + wsel * 1024;
        #pragma unroll
        for (int j = 0; j < 4; j++) {
            int idx = tid + j * 256;
            int n = idx >> 3;
            int cj = idx & 7;
            unsigned dst = n * 128 + ((cj * 16) ^ ((n & 7) << 4));
            *(uint4*)(smc + NO_BH + dst) = bh[idx];
            *(uint4*)(smc + NO_BL + dst) = bl[idx];
        }
    }

    const int w = tid >> 5;
    const int lane = tid & 31;
    const int m0 = (w & 3) * 32;
    const int nn0 = (w >> 2) * 64;
    const int rA0 = m0 + (lane & 15);
    const unsigned hiA = ((lane >> 4) & 1) << 4;
    const unsigned swA = (rA0 & 7) << 4;
    const int rB = nn0 + (lane & 7);
    const unsigned hiB = ((lane >> 3) & 1) << 4;
    const unsigned swB = (lane & 7) << 4;
    const unsigned boff = sb + NO_BH + rB * 128;
    const int cq = lane & 3;
    const int cbase = (w >> 2) * 32;

    for (int t = blockIdx.x; t < ntiles; t += 148) {
        int n0 = t * 128;
        __syncthreads();
        #pragma unroll
        for (int j = 0; j < 4; j++) {
            int idx = tid + j * 256;
            int e = idx >> 3;
            int cj = idx & 7;
            float4 v0, v1;
            if (n0 + e < n_nodes) {
                const float4* src = (const float4*)x + (size_t)(n0 + e) * 16 + cj * 2;
                v0 = src[0]; v1 = src[1];
            } else {
                v0 = make_float4(0.f, 0.f, 0.f, 0.f);
                v1 = v0;
            }
            float vv[8] = {v0.x, v0.y, v0.z, v0.w, v1.x, v1.y, v1.z, v1.w};
            unsigned H[4], L[4];
            #pragma unroll
            for (int p = 0; p < 4; p++) {
                __half h0 = __float2half_rn(vv[2 * p]);
                __half h1 = __float2half_rn(vv[2 * p + 1]);
                __half l0 = __float2half_rn(vv[2 * p] - __half2float(h0));
                __half l1 = __float2half_rn(vv[2 * p + 1] - __half2float(h1));
                H[p] = (unsigned)__half_as_ushort(h0) | ((unsigned)__half_as_ushort(h1) << 16);
                L[p] = (unsigned)__half_as_ushort(l0) | ((unsigned)__half_as_ushort(l1) << 16);
            }
            unsigned dst = e * 128 + ((cj * 16) ^ ((e & 7) << 4));
            *(uint4*)(smc + NO_AH + dst) = make_uint4(H[0], H[1], H[2], H[3]);
            *(uint4*)(smc + NO_AL + dst) = make_uint4(L[0], L[1], L[2], L[3]);
        }
        __syncthreads();

        float acc[2][8][4];
        #pragma unroll
        for (int mt = 0; mt < 2; mt++)
            #pragma unroll
            for (int nt = 0; nt < 8; nt++)
                #pragma unroll
                for (int p = 0; p < 4; p++) acc[mt][nt][p] = 0.0f;

        const unsigned aoff0 = sb + NO_AH + rA0 * 128;
        const unsigned aoff1 = aoff0 + 16 * 128;
        #pragma unroll
        for (int kc = 0; kc < 4; kc++) {
            unsigned ka = (unsigned)(kc * 32 + hiA) ^ swA;
            unsigned ah[4], ah2[4], al[4], al2[4];
            LDSM4(ah,  aoff0 + ka);
            LDSM4(ah2, aoff1 + ka);
            LDSM4(al,  aoff0 + ka + 16384);
            LDSM4(al2, aoff1 + ka + 16384);
            unsigned kb = (unsigned)(kc * 32 + hiB) ^ swB;
            #pragma unroll
            for (int nt = 0; nt < 8; nt++) {
                unsigned ba = boff + nt * 8 * 128 + kb;
                unsigned bh0, bh1, bl0, bl1;
                LDSM2(bh0, bh1, ba);
                LDSM2(bl0, bl1, ba + 16384);
                MMA16816(acc[0][nt], ah,  bh0, bh1);
                MMA16816(acc[1][nt], ah2, bh0, bh1);
                MMA16816(acc[0][nt], ah,  bl0, bl1);
                MMA16816(acc[1][nt], ah2, bl0, bl1);
                MMA16816(acc[0][nt], al,  bh0, bh1);
                MMA16816(acc[1][nt], al2, bh0, bh1);
            }
        }

        #pragma unroll
        for (int mt = 0; mt < 2; mt++) {
            int elo = m0 + mt * 16 + (lane >> 2);
            int ehi = elo + 8;
            #pragma unroll
            for (int nt = 0; nt < 8; nt++) {
                int c = cbase + nt * 4 + cq;
                if (n0 + elo < n_nodes)
                    *(unsigned*)(P + (size_t)(n0 + elo) * 128 + 2 * c) = pack_f16x2(acc[mt][nt][0], acc[mt][nt][1]);
                if (n0 + ehi < n_nodes)
                    *(unsigned*)(P + (size_t)(n0 + ehi) * 128 + 2 * c) = pack_f16x2(acc[mt][nt][2], acc[mt][nt][3]);
            }
        }
    }
}

// ---------------- edge kernel: A-tile software pipeline via cp.async ----------------
__global__ __launch_bounds__(256, 2)
void edge_mma_kernel(const float* __restrict__ ea,
                     const float* __restrict__ bfb,
                     const float* __restrict__ bsb,
                     const int*   __restrict__ esrc,
                     const int*   __restrict__ etgt,
                     int n_edges, int ntiles)
{
    extern __shared__ char smc[];
    unsigned sb = smem_u32(smc);
    int* s_src = (int*)(smc + EO_SRC);
    int* s_tgt = (int*)(smc + EO_TGT);
    unsigned* stage = (unsigned*)(smc + EO_STAGE);
    const unsigned* sp1 = (const unsigned*)(smc + EO_SP1);
    const unsigned* sp2 = (const unsigned*)(smc + EO_SP2);
    const int tid = threadIdx.x;
    const int w = tid >> 5;
    const int lane = tid & 31;
    const int mg = w >> 2;            // 0..1
    const int nq = w & 3;             // 0..3
    const int m0 = mg * 32;
    const int cq = lane & 3;

    // ---- bias into registers (pre-loaded into MMA accumulators) ----
    float bfv[4], bsv[4];
    {
        int c0 = nq * 16 + cq;
        #pragma unroll
        for (int nt = 0; nt < 4; nt++) {
            bfv[nt] = bfb[c0 + nt * 4];
            bsv[nt] = bsb[c0 + nt * 4];
        }
    }

    // ---- B fragments straight from gmem (once) ----
    unsigned bh_fr[4][4][2], bl_fr[4][4][2];
    {
        const unsigned short* BH = g_Bh + 2 * 8192;
        const unsigned short* BL = g_Bl + 2 * 8192;
        int nrow = nq * 32 + (lane >> 2);
        int k0 = (lane & 3) * 2;
        #pragma unroll
        for (int kc = 0; kc < 4; kc++) {
            #pragma unroll
            for (int nt = 0; nt < 4; nt++) {
                int off = (nrow + nt * 8) * 64 + kc * 16 + k0;
                bh_fr[kc][nt][0] = *(const unsigned*)(BH + off);
                bh_fr[kc][nt][1] = *(const unsigned*)(BH + off + 8);
                bl_fr[kc][nt][0] = *(const unsigned*)(BL + off);
                bl_fr[kc][nt][1] = *(const unsigned*)(BL + off + 8);
            }
        }
    }

    const int rA0 = m0 + (lane & 15);
    const unsigned hiA = ((lane >> 4) & 1) << 4;
    const unsigned swA = (rA0 & 7) << 4;
    const unsigned aoff0 = sb + EO_AH + rA0 * 128;
    const unsigned aoff1 = aoff0 + 16 * 128;
    const int li = lane & 7;
    const int egl = lane >> 3;

    // cp.async constants for P prefetch
    const int cp_e0 = tid >> 5;               // +8 per j
    const int cp_sel = (tid >> 4) & 1;
    const int cp_ch16 = (tid & 15) * 16;
    const unsigned short* cp_P = cp_sel ? g_P2h : g_P1h;
    const unsigned cp_dst0 = sb + (cp_sel ? EO_SP2 : EO_SP1) + cp_e0 * 256 + cp_ch16;

    // A-raw cp.async constants: 1024 chunks (e=idx>>4, ch=idx&15)
    const int ar_e = tid >> 2;                // edge for j stride handled below
    const int ar_ch = tid & 3;                // handled via idx math below

    int buf = 0;

    // ---- preload first tile's raw A + indices ----
    {
        int e0n = blockIdx.x * TILE_E;
        #pragma unroll
        for (int j = 0; j < 4; j++) {
            int idx = tid + j * 256;
            int e = idx >> 4;
            int ch = idx & 15;
            long long ge = e0n + e;
            if (ge > n_edges - 1) ge = n_edges - 1;
            CP_ASYNC16(sb + EO_ARAW + e * 256 + ch * 16,
                       (const char*)ea + ge * 256 + ch * 16);
        }
        if (tid < TILE_E) {
            int ge = e0n + tid;
            s_src[tid] = (ge < n_edges) ? esrc[ge] : 0;
        } else if (tid < 2 * TILE_E) {
            int tt = tid - TILE_E;
            int ge = e0n + tt;
            s_tgt[tt] = (ge < n_edges) ? etgt[ge] : 0;
        }
        CP_COMMIT();
        CP_WAIT0();
        __syncthreads();
    }

    for (int t = blockIdx.x; t < ntiles; t += gridDim.x) {
        const int e0 = t * TILE_E;
        const int tn = t + gridDim.x;

        // ---- 1. P prefetch for tile t ----
        {
            const int* cp_idx = (cp_sel ? s_tgt : s_src) + buf * TILE_E;
            #pragma unroll
            for (int j = 0; j < 8; j++) {
                int node = cp_idx[cp_e0 + j * 8];
                const char* srcp = (const char*)(cp_P + (size_t)node * 128) + cp_ch16;
                CP_ASYNC16(cp_dst0 + j * 2048, srcp);
            }
        }
        // ---- 2. A raw + idx prefetch for tile tn ----
        if (tn < ntiles) {
            int e0n = tn * TILE_E;
            unsigned adst = sb + EO_ARAW + (buf ^ 1) * 16384;
            #pragma unroll
            for (int j = 0; j < 4; j++) {
                int idx = tid + j * 256;
                int e = idx >> 4;
                int ch = idx & 15;
                long long ge = e0n + e;
                if (ge > n_edges - 1) ge = n_edges - 1;
                CP_ASYNC16(adst + e * 256 + ch * 16,
                           (const char*)ea + ge * 256 + ch * 16);
            }
            if (tid < TILE_E) {
                int ge = e0n + tid;
                s_src[(buf ^ 1) * TILE_E + tid] = (ge < n_edges) ? esrc[ge] : 0;
            } else if (tid < 2 * TILE_E) {
                int tt = tid - TILE_E;
                int ge = e0n + tt;
                s_tgt[(buf ^ 1) * TILE_E + tt] = (ge < n_edges) ? etgt[ge] : 0;
            }
        }
        CP_COMMIT();

        // ---- 3. convert A raw (smem) -> fp16 swizzled AH ----
        {
            const char* araw = smc + EO_ARAW + buf * 16384;
            #pragma unroll
            for (int j = 0; j < 2; j++) {
                int idx = tid + j * 256;
                int e = idx >> 3;
                int cj = idx & 7;
                float4 v0 = *(const float4*)(araw + e * 256 + cj * 32);
                float4 v1 = *(const float4*)(araw + e * 256 + cj * 32 + 16);
                unsigned H[4];
                H[0] = pack_f16x2(v0.x, v0.y);
                H[1] = pack_f16x2(v0.z, v0.w);
                H[2] = pack_f16x2(v1.x, v1.y);
                H[3] = pack_f16x2(v1.z, v1.w);
                unsigned dst = e * 128 + ((cj * 16) ^ ((e & 7) << 4));
                *(uint4*)(smc + EO_AH + dst) = make_uint4(H[0], H[1], H[2], H[3]);
            }
        }
        __syncthreads();

        // ---- 4. mma mainloop (acc pre-loaded with bias) ----
        float acc[2][4][4];
        #pragma unroll
        for (int mt = 0; mt < 2; mt++)
            #pragma unroll
            for (int nt = 0; nt < 4; nt++) {
                acc[mt][nt][0] = bfv[nt];
                acc[mt][nt][1] = bsv[nt];
                acc[mt][nt][2] = bfv[nt];
                acc[mt][nt][3] = bsv[nt];
            }

        #pragma unroll
        for (int kc = 0; kc < 4; kc++) {
            unsigned ka = (unsigned)(kc * 32 + hiA) ^ swA;
            unsigned ah[4], ah2[4];
            LDSM4(ah,  aoff0 + ka);
            LDSM4(ah2, aoff1 + ka);
            #pragma unroll
            for (int nt = 0; nt < 4; nt++) {
                MMA16816(acc[0][nt], ah,  bh_fr[kc][nt][0], bh_fr[kc][nt][1]);
                MMA16816(acc[1][nt], ah2, bh_fr[kc][nt][0], bh_fr[kc][nt][1]);
                MMA16816(acc[0][nt], ah,  bl_fr[kc][nt][0], bl_fr[kc][nt][1]);
                MMA16816(acc[1][nt], ah2, bl_fr[kc][nt][0], bl_fr[kc][nt][1]);
            }
        }

        // ---- 5. stage raw (g,v)+bias as packed fp16 ----
        #pragma unroll
        for (int mt = 0; mt < 2; mt++) {
            int elo = m0 + mt * 16 + (lane >> 2);
            int ehi = elo + 8;
            #pragma unroll
            for (int nt = 0; nt < 4; nt++) {
                int c = nq * 16 + nt * 4 + cq;
                stage[elo * STGU + c] = pack_f16x2(acc[mt][nt][0], acc[mt][nt][1]);
                stage[ehi * STGU + c] = pack_f16x2(acc[mt][nt][2], acc[mt][nt][3]);
            }
        }
        CP_WAIT0();
        __syncthreads();

        // ---- 6. per-edge epilogue: half2 sums, activations, scatter ----
        const int* s_src_b = s_src + buf * TILE_E;
        #pragma unroll
        for (int g2 = 0; g2 < 2; g2++) {
            int el = w * 8 + g2 * 4 + egl;
            int ge = e0 + el;
            int src = s_src_b[el];
            #pragma unroll
            for (int q = 0; q < 2; q++) {
                int cc = q * 32 + li * 4;
                uint4 st = *(const uint4*)(stage + el * STGU + cc);
                uint4 p1 = *(const uint4*)(sp1 + el * 64 + cc);
                uint4 p2 = *(const uint4*)(sp2 + el * 64 + cc);
                unsigned u0 = hadd2u(hadd2u(st.x, p1.x), p2.x);
                unsigned u1 = hadd2u(hadd2u(st.y, p1.y), p2.y);
                unsigned u2 = hadd2u(hadd2u(st.z, p1.z), p2.z);
                unsigned u3 = hadd2u(hadd2u(st.w, p1.w), p2.w);
                float2 f0 = unpack_h2(u0), f1 = unpack_h2(u1), f2 = unpack_h2(u2), f3 = unpack_h2(u3);
                float m0v = sigmoid_f(f0.x) * softplus_f(f0.y);
                float m1v = sigmoid_f(f1.x) * softplus_f(f1.y);
                float m2v = sigmoid_f(f2.x) * softplus_f(f2.y);
                float m3v = sigmoid_f(f3.x) * softplus_f(f3.y);
                if (ge < n_edges) {
                    float* dst = g_message + (size_t)src * 64 + cc;
                    asm volatile("red.global.add.v4.f32 [%0], {%1, %2, %3, %4};"
                                 :: "l"(dst), "f"(m0v), "f"(m1v), "f"(m2v), "f"(m3v)
                                 : "memory");
                }
            }
        }
        __syncthreads();
        buf ^= 1;
    }
}

// ---------------- stats ----------------
__global__ __launch_bounds__(256)
void stats_kernel(int n4) {
    int t = blockIdx.x * blockDim.x + threadIdx.x;
    int stride = gridDim.x * blockDim.x;
    const float4* m4 = (const float4*)g_message;
    float4 s = make_float4(0.f, 0.f, 0.f, 0.f);
    float4 q = make_float4(0.f, 0.f, 0.f, 0.f);
    for (int i = t; i < n4; i += stride) {
        float4 v = m4[i];
        s.x += v.x; s.y += v.y; s.z += v.z; s.w += v.w;
        q.x += v.x * v.x; q.y += v.y * v.y; q.z += v.z * v.z; q.w += v.w * v.w;
    }
    __shared__ float4 ss[256];
    __shared__ float4 qq[256];
    ss[threadIdx.x] = s;
    qq[threadIdx.x] = q;
    __syncthreads();
    #pragma unroll
    for (int off = 128; off >= 16; off >>= 1) {
        if (threadIdx.x < off) {
            float4 a = ss[threadIdx.x + off], b = qq[threadIdx.x + off];
            float4 sa = ss[threadIdx.x], qa = qq[threadIdx.x];
            sa.x += a.x; sa.y += a.y; sa.z += a.z; sa.w += a.w;
            qa.x += b.x; qa.y += b.y; qa.z += b.z; qa.w += b.w;
            ss[threadIdx.x] = sa;
            qq[threadIdx.x] = qa;
        }
        __syncthreads();
    }
    if (threadIdx.x < 16) {
        int c = threadIdx.x * 4;
        float4 sa = ss[threadIdx.x], qa = qq[threadIdx.x];
        atomicAdd(&g_sum[c + 0], sa.x); atomicAdd(&g_sum[c + 1], sa.y);
        atomicAdd(&g_sum[c + 2], sa.z); atomicAdd(&g_sum[c + 3], sa.w);
        atomicAdd(&g_sumsq[c + 0], qa.x); atomicAdd(&g_sumsq[c + 1], qa.y);
        atomicAdd(&g_sumsq[c + 2], qa.z); atomicAdd(&g_sumsq[c + 3], qa.w);
    }
}

// ---------------- final ----------------
__global__ __launch_bounds__(256)
void final_kernel(const float* __restrict__ x,
                  const float* __restrict__ gamma,
                  const float* __restrict__ beta,
                  float* __restrict__ out,
                  int n4, float inv_n)
{
    int i = blockIdx.x * blockDim.x + threadIdx.x;
    if (i >= n4) return;
    int c = (i & 15) * 4;
    float4 mm = ((const float4*)g_message)[i];
    float4 xx = ((const float4*)x)[i];
    float4 gm = ((const float4*)gamma)[i & 15];
    float4 bt = ((const float4*)beta)[i & 15];
    float mv[4] = {mm.x, mm.y, mm.z, mm.w};
    float xv[4] = {xx.x, xx.y, xx.z, xx.w};
    float gv[4] = {gm.x, gm.y, gm.z, gm.w};
    float bv[4] = {bt.x, bt.y, bt.z, bt.w};
    float ov[4];
    #pragma unroll
    for (int j = 0; j < 4; j++) {
        float mean = g_sum[c + j] * inv_n;
        float var  = g_sumsq[c + j] * inv_n - mean * mean;
        float inv_std = rsqrtf(var + 1e-5f);
        float mn = (mv[j] - mean) * inv_std * gv[j] + bv[j];
        float t = xv[j] + mn;
        ov[j] = fmaxf(t, 0.0f) + log1pf(expf(-fabsf(t)));
    }
    ((float4*)out)[i] = make_float4(ov[0], ov[1], ov[2], ov[3]);
}

extern "C" void kernel_launch(void* const* d_in, const int* in_sizes, int n_in,
                              void* d_out, int out_size)
{
    const float* x     = (const float*)d_in[0];
    const float* ea    = (const float*)d_in[1];
    const float* Wf    = (const float*)d_in[2];
    const float* bf    = (const float*)d_in[3];
    const float* Ws    = (const float*)d_in[4];
    const float* bs    = (const float*)d_in[5];
    const float* gamma = (const float*)d_in[6];
    const float* beta  = (const float*)d_in[7];
    const int*   esrc  = (const int*)d_in[8];
    const int*   etgt  = (const int*)d_in[9];
    float* out = (float*)d_out;

    int n_nodes = in_sizes[0] / DCH;
    int n_edges = in_sizes[8];
    int total   = n_nodes * DCH;
    int total4  = total / 4;
    int etiles  = (n_edges + TILE_E - 1) / TILE_E;
    int ntiles  = (n_nodes + 127) / 128;

    static bool attr_set = false;
    if (!attr_set) {
        cudaFuncSetAttribute(edge_mma_kernel, cudaFuncAttributeMaxDynamicSharedMemorySize, EDGE_SMEM_BYTES);
        cudaFuncSetAttribute(node_mma_kernel, cudaFuncAttributeMaxDynamicSharedMemorySize, NODE_SMEM_BYTES);
        attr_set = true;
    }

    {   // 1
        int grid = (total4 + 255) / 256;
        if (grid > 1024) grid = 1024;
        zero_kernel<<<grid, 256>>>(total4);
    }
    prep_B_kernel<<<96, 256>>>(Wf, Ws);                                      // 2
    {   // 3
        dim3 grid(148, 2);
        node_mma_kernel<<<grid, 256, NODE_SMEM_BYTES>>>(x, n_nodes, ntiles);
    }
    {   // 4  <- ncu slot
        int grid = 296;
        if (grid > etiles) grid = etiles;
        edge_mma_kernel<<<grid, 256, EDGE_SMEM_BYTES>>>(ea, bf, bs, esrc, etgt, n_edges, etiles);
    }
    stats_kernel<<<512, 256>>>(total4);                                      // 5
    {   // 6
        int grid = (total4 + 255) / 256;
        final_kernel<<<grid, 256>>>(x, gamma, beta, out, total4, 1.0f / (float)n_nodes);
    }
}

// round 15
// speedup vs baseline: 1.6134x; 1.0458x over previous
#include <cuda_runtime.h>
#include <cuda_fp16.h>
#include <math.h>

#define DCH    64
#define FAN    192
#define TILE_E 32
#define MAX_NODES 50176

__device__ float g_message[MAX_NODES * DCH];
__device__ unsigned short g_P1h[MAX_NODES * 128];
__device__ unsigned short g_P2h[MAX_NODES * 128];
__device__ float g_sum[DCH];
__device__ float g_sumsq[DCH];
__device__ unsigned short g_Bh[3 * 128 * 64];
__device__ unsigned short g_Bl[3 * 128 * 64];

// ---------------- edge kernel smem (bytes) ----------------
#define EO_SRC   0                 // 2 bufs x 32 ints = 256
#define EO_TGT   256               // 256
#define EO_ARAW  512               // 2 x 8192 = 16384
#define EO_AH    16896             // 4096
#define EO_STAGE 20992             // 32 x 68 u32 = 8704
#define STGU     68
#define EO_SP1   29696             // 32 x 68 u32 = 8704 (padded rows, 272B)
#define EO_SP2   38400             // 8704
#define SPU      68
#define EDGE_SMEM_BYTES 47104

// ---------------- node kernel smem ----------------
#define NO_AH    0
#define NO_AL    16384
#define NO_BH    32768
#define NO_BL    49152
#define NODE_SMEM_BYTES 65536

// ---------------- helpers ----------------
__device__ __forceinline__ unsigned smem_u32(const void* p) {
    unsigned a;
    asm("{ .reg .u64 t; cvta.to.shared.u64 t, %1; cvt.u32.u64 %0, t; }" : "=r"(a) : "l"(p));
    return a;
}
__device__ __forceinline__ unsigned pack_f16x2(float lo, float hi) {
    unsigned r;
    asm("cvt.rn.f16x2.f32 %0, %1, %2;" : "=r"(r) : "f"(hi), "f"(lo));
    return r;
}
__device__ __forceinline__ unsigned hadd2u(unsigned a, unsigned b) {
    unsigned d;
    asm("add.rn.f16x2 %0, %1, %2;" : "=r"(d) : "r"(a), "r"(b));
    return d;
}
__device__ __forceinline__ float2 unpack_h2(unsigned u) {
    __half2 h = *reinterpret_cast<__half2*>(&u);
    return __half22float2(h);
}
__device__ __forceinline__ float ex2a(float x) { float r; asm("ex2.approx.f32 %0, %1;" : "=f"(r) : "f"(x)); return r; }
__device__ __forceinline__ float lg2a(float x) { float r; asm("lg2.approx.f32 %0, %1;" : "=f"(r) : "f"(x)); return r; }
__device__ __forceinline__ float sigmoid_f(float g) {
    float t;
    asm("tanh.approx.f32 %0, %1;" : "=f"(t) : "f"(g * 0.5f));
    return fmaf(t, 0.5f, 0.5f);
}
__device__ __forceinline__ float softplus_f(float v) {
    float u = ex2a(-1.44269504f * fabsf(v));
    return fmaxf(v, 0.0f) + 0.69314718f * lg2a(1.0f + u);
}

#define LDSM4(R, A) \
    asm volatile("ldmatrix.sync.aligned.m8n8.x4.shared.b16 {%0,%1,%2,%3}, [%4];" \
        : "=r"((R)[0]), "=r"((R)[1]), "=r"((R)[2]), "=r"((R)[3]) : "r"(A))
#define LDSM2(R0, R1, A) \
    asm volatile("ldmatrix.sync.aligned.m8n8.x2.shared.b16 {%0,%1}, [%2];" \
        : "=r"(R0), "=r"(R1) : "r"(A))
#define MMA16816(D, A, B0, B1) \
    asm volatile("mma.sync.aligned.m16n8k16.row.col.f32.f16.f16.f32 " \
        "{%0,%1,%2,%3}, {%4,%5,%6,%7}, {%8,%9}, {%0,%1,%2,%3};" \
        : "+f"((D)[0]), "+f"((D)[1]), "+f"((D)[2]), "+f"((D)[3]) \
        : "r"((A)[0]), "r"((A)[1]), "r"((A)[2]), "r"((A)[3]), "r"(B0), "r"(B1))
#define CP_ASYNC16(dst, src) \
    asm volatile("cp.async.cg.shared.global [%0], [%1], 16;" :: "r"(dst), "l"(src))
#define CP_COMMIT() asm volatile("cp.async.commit_group;" ::: "memory")
#define CP_WAIT0()  asm volatile("cp.async.wait_group 0;" ::: "memory")

// ---------------- prep: all 3 W slices -> fp16 hi/lo ----------------
__global__ void prep_B_kernel(const float* __restrict__ Wf, const float* __restrict__ Ws) {
    int idx = blockIdx.x * 256 + threadIdx.x;   // 24576
    int s = idx >> 13;
    int r = idx & 8191;
    int n = r >> 6;
    int k = r & 63;
    int d = n >> 1;
    const float* w = (n & 1) ? Ws : Wf;
    float v = w[d * FAN + s * 64 + k];
    __half h = __float2half_rn(v);
    __half l = __float2half_rn(v - __half2float(h));
    g_Bh[idx] = __half_as_ushort(h);
    g_Bl[idx] = __half_as_ushort(l);
}

// ---------------- zero ----------------
__global__ void zero_kernel(int total4) {
    int i = blockIdx.x * blockDim.x + threadIdx.x;
    int stride = gridDim.x * blockDim.x;
    float4* m4 = (float4*)g_message;
    for (int j = i; j < total4; j += stride) m4[j] = make_float4(0.f, 0.f, 0.f, 0.f);
    if (i < DCH) { g_sum[i] = 0.0f; g_sumsq[i] = 0.0f; }
}

// ---------------- node projections on tensor cores -> fp16 P ----------------
__global__ __launch_bounds__(256, 2)
void node_mma_kernel(const float* __restrict__ x, int n_nodes, int ntiles)
{
    extern __shared__ char smc[];
    unsigned sb = smem_u32(smc);
    const int tid = threadIdx.x;
    const int wsel = blockIdx.y;
    unsigned short* P = wsel ? g_P2h : g_P1h;

    {
        const uint4* bh = (const uint4*)g_Bh + wsel * 1024;
        const uint4* bl = (const uint4*)g_Bl + wsel * 1024;
        #pragma unroll
        for (int j = 0; j < 4; j++) {
            int idx = tid + j * 256;
            int n = idx >> 3;
            int cj = idx & 7;
            unsigned dst = n * 128 + ((cj * 16) ^ ((n & 7) << 4));
            *(uint4*)(smc + NO_BH + dst) = bh[idx];
            *(uint4*)(smc + NO_BL + dst) = bl[idx];
        }
    }

    const int w = tid >> 5;
    const int lane = tid & 31;
    const int m0 = (w & 3) * 32;
    const int nn0 = (w >> 2) * 64;
    const int rA0 = m0 + (lane & 15);
    const unsigned hiA = ((lane >> 4) & 1) << 4;
    const unsigned swA = (rA0 & 7) << 4;
    const int rB = nn0 + (lane & 7);
    const unsigned hiB = ((lane >> 3) & 1) << 4;
    const unsigned swB = (lane & 7) << 4;
    const unsigned boff = sb + NO_BH + rB * 128;
    const int cq = lane & 3;
    const int cbase = (w >> 2) * 32;

    for (int t = blockIdx.x; t < ntiles; t += 148) {
        int n0 = t * 128;
        __syncthreads();
        #pragma unroll
        for (int j = 0; j < 4; j++) {
            int idx = tid + j * 256;
            int e = idx >> 3;
            int cj = idx & 7;
            float4 v0, v1;
            if (n0 + e < n_nodes) {
                const float4* src = (const float4*)x + (size_t)(n0 + e) * 16 + cj * 2;
                v0 = src[0]; v1 = src[1];
            } else {
                v0 = make_float4(0.f, 0.f, 0.f, 0.f);
                v1 = v0;
            }
            float vv[8] = {v0.x, v0.y, v0.z, v0.w, v1.x, v1.y, v1.z, v1.w};
            unsigned H[4], L[4];
            #pragma unroll
            for (int p = 0; p < 4; p++) {
                __half h0 = __float2half_rn(vv[2 * p]);
                __half h1 = __float2half_rn(vv[2 * p + 1]);
                __half l0 = __float2half_rn(vv[2 * p] - __half2float(h0));
                __half l1 = __float2half_rn(vv[2 * p + 1] - __half2float(h1));
                H[p] = (unsigned)__half_as_ushort(h0) | ((unsigned)__half_as_ushort(h1) << 16);
                L[p] = (unsigned)__half_as_ushort(l0) | ((unsigned)__half_as_ushort(l1) << 16);
            }
            unsigned dst = e * 128 + ((cj * 16) ^ ((e & 7) << 4));
            *(uint4*)(smc + NO_AH + dst) = make_uint4(H[0], H[1], H[2], H[3]);
            *(uint4*)(smc + NO_AL + dst) = make_uint4(L[0], L[1], L[2], L[3]);
        }
        __syncthreads();

        float acc[2][8][4];
        #pragma unroll
        for (int mt = 0; mt < 2; mt++)
            #pragma unroll
            for (int nt = 0; nt < 8; nt++)
                #pragma unroll
                for (int p = 0; p < 4; p++) acc[mt][nt][p] = 0.0f;

        const unsigned aoff0 = sb + NO_AH + rA0 * 128;
        const unsigned aoff1 = aoff0 + 16 * 128;
        #pragma unroll
        for (int kc = 0; kc < 4; kc++) {
            unsigned ka = (unsigned)(kc * 32 + hiA) ^ swA;
            unsigned ah[4], ah2[4], al[4], al2[4];
            LDSM4(ah,  aoff0 + ka);
            LDSM4(ah2, aoff1 + ka);
            LDSM4(al,  aoff0 + ka + 16384);
            LDSM4(al2, aoff1 + ka + 16384);
            unsigned kb = (unsigned)(kc * 32 + hiB) ^ swB;
            #pragma unroll
            for (int nt = 0; nt < 8; nt++) {
                unsigned ba = boff + nt * 8 * 128 + kb;
                unsigned bh0, bh1, bl0, bl1;
                LDSM2(bh0, bh1, ba);
                LDSM2(bl0, bl1, ba + 16384);
                MMA16816(acc[0][nt], ah,  bh0, bh1);
                MMA16816(acc[1][nt], ah2, bh0, bh1);
                MMA16816(acc[0][nt], ah,  bl0, bl1);
                MMA16816(acc[1][nt], ah2, bl0, bl1);
                MMA16816(acc[0][nt], al,  bh0, bh1);
                MMA16816(acc[1][nt], al2, bh0, bh1);
            }
        }

        #pragma unroll
        for (int mt = 0; mt < 2; mt++) {
            int elo = m0 + mt * 16 + (lane >> 2);
            int ehi = elo + 8;
            #pragma unroll
            for (int nt = 0; nt < 8; nt++) {
                int c = cbase + nt * 4 + cq;
                if (n0 + elo < n_nodes)
                    *(unsigned*)(P + (size_t)(n0 + elo) * 128 + 2 * c) = pack_f16x2(acc[mt][nt][0], acc[mt][nt][1]);
                if (n0 + ehi < n_nodes)
                    *(unsigned*)(P + (size_t)(n0 + ehi) * 128 + 2 * c) = pack_f16x2(acc[mt][nt][2], acc[mt][nt][3]);
            }
        }
    }
}

// ---------------- edge kernel: 128 threads, 32-edge tile, 4 CTAs/SM ----------------
__global__ __launch_bounds__(128, 4)
void edge_mma_kernel(const float* __restrict__ ea,
                     const float* __restrict__ bfb,
                     const float* __restrict__ bsb,
                     const int*   __restrict__ esrc,
                     const int*   __restrict__ etgt,
                     int n_edges, int ntiles)
{
    extern __shared__ char smc[];
    unsigned sb = smem_u32(smc);
    int* s_src = (int*)(smc + EO_SRC);
    int* s_tgt = (int*)(smc + EO_TGT);
    unsigned* stage = (unsigned*)(smc + EO_STAGE);
    const unsigned* sp1 = (const unsigned*)(smc + EO_SP1);
    const unsigned* sp2 = (const unsigned*)(smc + EO_SP2);
    const int tid = threadIdx.x;
    const int w = tid >> 5;          // 0..3 = nq
    const int lane = tid & 31;
    const int nq = w;
    const int cq = lane & 3;

    // ---- bias into registers ----
    float bfv[4], bsv[4];
    {
        int c0 = nq * 16 + cq;
        #pragma unroll
        for (int nt = 0; nt < 4; nt++) {
            bfv[nt] = bfb[c0 + nt * 4];
            bsv[nt] = bsb[c0 + nt * 4];
        }
    }

    // ---- B fragments straight from gmem (once) ----
    unsigned bh_fr[4][4][2], bl_fr[4][4][2];
    {
        const unsigned short* BH = g_Bh + 2 * 8192;
        const unsigned short* BL = g_Bl + 2 * 8192;
        int nrow = nq * 32 + (lane >> 2);
        int k0 = (lane & 3) * 2;
        #pragma unroll
        for (int kc = 0; kc < 4; kc++) {
            #pragma unroll
            for (int nt = 0; nt < 4; nt++) {
                int off = (nrow + nt * 8) * 64 + kc * 16 + k0;
                bh_fr[kc][nt][0] = *(const unsigned*)(BH + off);
                bh_fr[kc][nt][1] = *(const unsigned*)(BH + off + 8);
                bl_fr[kc][nt][0] = *(const unsigned*)(BL + off);
                bl_fr[kc][nt][1] = *(const unsigned*)(BL + off + 8);
            }
        }
    }

    const int rA0 = lane & 15;
    const unsigned hiA = ((lane >> 4) & 1) << 4;
    const unsigned swA = (rA0 & 7) << 4;
    const unsigned aoff0 = sb + EO_AH + rA0 * 128;
    const unsigned aoff1 = aoff0 + 16 * 128;
    const int li = lane & 7;
    const int egl = lane >> 3;

    // P-prefetch constants: 1024 16B chunks, 8 per thread
    const int cp_e0 = tid >> 5;               // 0..3, +4 per j
    const int cp_sel = (tid >> 4) & 1;
    const int cp_ch16 = (tid & 15) * 16;
    const unsigned short* cp_P = cp_sel ? g_P2h : g_P1h;
    const unsigned cp_dst0 = sb + (cp_sel ? EO_SP2 : EO_SP1) + cp_e0 * 272 + cp_ch16;

    int buf = 0;

    // ---- preload first tile's raw A + indices ----
    {
        int e0n = blockIdx.x * TILE_E;
        #pragma unroll
        for (int j = 0; j < 4; j++) {
            int idx = tid + j * 128;           // 512 chunks
            int e = idx >> 4;
            int ch = idx & 15;
            long long ge = e0n + e;
            if (ge > n_edges - 1) ge = n_edges - 1;
            CP_ASYNC16(sb + EO_ARAW + e * 256 + ch * 16,
                       (const char*)ea + ge * 256 + ch * 16);
        }
        if (tid < TILE_E) {
            int ge = e0n + tid;
            s_src[tid] = (ge < n_edges) ? esrc[ge] : 0;
        } else if (tid < 2 * TILE_E) {
            int tt = tid - TILE_E;
            int ge = e0n + tt;
            s_tgt[tt] = (ge < n_edges) ? etgt[ge] : 0;
        }
        CP_COMMIT();
        CP_WAIT0();
        __syncthreads();
    }

    for (int t = blockIdx.x; t < ntiles; t += gridDim.x) {
        const int e0 = t * TILE_E;
        const int tn = t + gridDim.x;

        // ---- 1. P prefetch for tile t ----
        {
            const int* cp_idx = (cp_sel ? s_tgt : s_src) + buf * TILE_E;
            #pragma unroll
            for (int j = 0; j < 8; j++) {
                int node = cp_idx[cp_e0 + j * 4];
                const char* srcp = (const char*)(cp_P + (size_t)node * 128) + cp_ch16;
                CP_ASYNC16(cp_dst0 + j * 1088, srcp);
            }
        }
        // ---- 2. A raw + idx prefetch for tile tn ----
        if (tn < ntiles) {
            int e0n = tn * TILE_E;
            unsigned adst = sb + EO_ARAW + (buf ^ 1) * 8192;
            #pragma unroll
            for (int j = 0; j < 4; j++) {
                int idx = tid + j * 128;
                int e = idx >> 4;
                int ch = idx & 15;
                long long ge = e0n + e;
                if (ge > n_edges - 1) ge = n_edges - 1;
                CP_ASYNC16(adst + e * 256 + ch * 16,
                           (const char*)ea + ge * 256 + ch * 16);
            }
            if (tid < TILE_E) {
                int ge = e0n + tid;
                s_src[(buf ^ 1) * TILE_E + tid] = (ge < n_edges) ? esrc[ge] : 0;
            } else if (tid < 2 * TILE_E) {
                int tt = tid - TILE_E;
                int ge = e0n + tt;
                s_tgt[(buf ^ 1) * TILE_E + tt] = (ge < n_edges) ? etgt[ge] : 0;
            }
        }
        CP_COMMIT();

        // ---- 3. convert A raw (smem) -> fp16 swizzled AH ----
        {
            const char* araw = smc + EO_ARAW + buf * 8192;
            #pragma unroll
            for (int j = 0; j < 2; j++) {
                int idx = tid + j * 128;       // 256 chunks
                int e = idx >> 3;
                int cj = idx & 7;
                float4 v0 = *(const float4*)(araw + e * 256 + cj * 32);
                float4 v1 = *(const float4*)(araw + e * 256 + cj * 32 + 16);
                unsigned H[4];
                H[0] = pack_f16x2(v0.x, v0.y);
                H[1] = pack_f16x2(v0.z, v0.w);
                H[2] = pack_f16x2(v1.x, v1.y);
                H[3] = pack_f16x2(v1.z, v1.w);
                unsigned dst = e * 128 + ((cj * 16) ^ ((e & 7) << 4));
                *(uint4*)(smc + EO_AH + dst) = make_uint4(H[0], H[1], H[2], H[3]);
            }
        }
        __syncthreads();

        // ---- 4. mma mainloop (acc pre-loaded with bias) ----
        float acc[2][4][4];
        #pragma unroll
        for (int mt = 0; mt < 2; mt++)
            #pragma unroll
            for (int nt = 0; nt < 4; nt++) {
                acc[mt][nt][0] = bfv[nt];
                acc[mt][nt][1] = bsv[nt];
                acc[mt][nt][2] = bfv[nt];
                acc[mt][nt][3] = bsv[nt];
            }

        #pragma unroll
        for (int kc = 0; kc < 4; kc++) {
            unsigned ka = (unsigned)(kc * 32 + hiA) ^ swA;
            unsigned ah[4], ah2[4];
            LDSM4(ah,  aoff0 + ka);
            LDSM4(ah2, aoff1 + ka);
            #pragma unroll
            for (int nt = 0; nt < 4; nt++) {
                MMA16816(acc[0][nt], ah,  bh_fr[kc][nt][0], bh_fr[kc][nt][1]);
                MMA16816(acc[1][nt], ah2, bh_fr[kc][nt][0], bh_fr[kc][nt][1]);
                MMA16816(acc[0][nt], ah,  bl_fr[kc][nt][0], bl_fr[kc][nt][1]);
                MMA16816(acc[1][nt], ah2, bl_fr[kc][nt][0], bl_fr[kc][nt][1]);
            }
        }

        // ---- 5. stage (g,v)+bias as packed fp16 ----
        #pragma unroll
        for (int mt = 0; mt < 2; mt++) {
            int elo = mt * 16 + (lane >> 2);
            int ehi = elo + 8;
            #pragma unroll
            for (int nt = 0; nt < 4; nt++) {
                int c = nq * 16 + nt * 4 + cq;
                stage[elo * STGU + c] = pack_f16x2(acc[mt][nt][0], acc[mt][nt][1]);
                stage[ehi * STGU + c] = pack_f16x2(acc[mt][nt][2], acc[mt][nt][3]);
            }
        }
        CP_WAIT0();
        __syncthreads();

        // ---- 6. per-edge epilogue ----
        const int* s_src_b = s_src + buf * TILE_E;
        #pragma unroll
        for (int g2 = 0; g2 < 2; g2++) {
            int el = w * 8 + g2 * 4 + egl;
            int ge = e0 + el;
            int src = s_src_b[el];
            #pragma unroll
            for (int q = 0; q < 2; q++) {
                int cc = q * 32 + li * 4;
                uint4 st = *(const uint4*)(stage + el * STGU + cc);
                uint4 p1 = *(const uint4*)(sp1 + el * SPU + cc);
                uint4 p2 = *(const uint4*)(sp2 + el * SPU + cc);
                unsigned u0 = hadd2u(hadd2u(st.x, p1.x), p2.x);
                unsigned u1 = hadd2u(hadd2u(st.y, p1.y), p2.y);
                unsigned u2 = hadd2u(hadd2u(st.z, p1.z), p2.z);
                unsigned u3 = hadd2u(hadd2u(st.w, p1.w), p2.w);
                float2 f0 = unpack_h2(u0), f1 = unpack_h2(u1), f2 = unpack_h2(u2), f3 = unpack_h2(u3);
                float m0v = sigmoid_f(f0.x) * softplus_f(f0.y);
                float m1v = sigmoid_f(f1.x) * softplus_f(f1.y);
                float m2v = sigmoid_f(f2.x) * softplus_f(f2.y);
                float m3v = sigmoid_f(f3.x) * softplus_f(f3.y);
                if (ge < n_edges) {
                    float* dst = g_message + (size_t)src * 64 + cc;
                    asm volatile("red.global.add.v4.f32 [%0], {%1, %2, %3, %4};"
                                 :: "l"(dst), "f"(m0v), "f"(m1v), "f"(m2v), "f"(m3v)
                                 : "memory");
                }
            }
        }
        __syncthreads();
        buf ^= 1;
    }
}

// ---------------- stats ----------------
__global__ __launch_bounds__(256)
void stats_kernel(int n4) {
    int t = blockIdx.x * blockDim.x + threadIdx.x;
    int stride = gridDim.x * blockDim.x;
    const float4* m4 = (const float4*)g_message;
    float4 s = make_float4(0.f, 0.f, 0.f, 0.f);
    float4 q = make_float4(0.f, 0.f, 0.f, 0.f);
    for (int i = t; i < n4; i += stride) {
        float4 v = m4[i];
        s.x += v.x; s.y += v.y; s.z += v.z; s.w += v.w;
        q.x += v.x * v.x; q.y += v.y * v.y; q.z += v.z * v.z; q.w += v.w * v.w;
    }
    __shared__ float4 ss[256];
    __shared__ float4 qq[256];
    ss[threadIdx.x] = s;
    qq[threadIdx.x] = q;
    __syncthreads();
    #pragma unroll
    for (int off = 128; off >= 16; off >>= 1) {
        if (threadIdx.x < off) {
            float4 a = ss[threadIdx.x + off], b = qq[threadIdx.x + off];
            float4 sa = ss[threadIdx.x], qa = qq[threadIdx.x];
            sa.x += a.x; sa.y += a.y; sa.z += a.z; sa.w += a.w;
            qa.x += b.x; qa.y += b.y; qa.z += b.z; qa.w += b.w;
            ss[threadIdx.x] = sa;
            qq[threadIdx.x] = qa;
        }
        __syncthreads();
    }
    if (threadIdx.x < 16) {
        int c = threadIdx.x * 4;
        float4 sa = ss[threadIdx.x], qa = qq[threadIdx.x];
        atomicAdd(&g_sum[c + 0], sa.x); atomicAdd(&g_sum[c + 1], sa.y);
        atomicAdd(&g_sum[c + 2], sa.z); atomicAdd(&g_sum[c + 3], sa.w);
        atomicAdd(&g_sumsq[c + 0], qa.x); atomicAdd(&g_sumsq[c + 1], qa.y);
        atomicAdd(&g_sumsq[c + 2], qa.z); atomicAdd(&g_sumsq[c + 3], qa.w);
    }
}

// ---------------- final ----------------
__global__ __launch_bounds__(256)
void final_kernel(const float* __restrict__ x,
                  const float* __restrict__ gamma,
                  const float* __restrict__ beta,
                  float* __restrict__ out,
                  int n4, float inv_n)
{
    int i = blockIdx.x * blockDim.x + threadIdx.x;
    if (i >= n4) return;
    int c = (i & 15) * 4;
    float4 mm = ((const float4*)g_message)[i];
    float4 xx = ((const float4*)x)[i];
    float4 gm = ((const float4*)gamma)[i & 15];
    float4 bt = ((const float4*)beta)[i & 15];
    float mv[4] = {mm.x, mm.y, mm.z, mm.w};
    float xv[4] = {xx.x, xx.y, xx.z, xx.w};
    float gv[4] = {gm.x, gm.y, gm.z, gm.w};
    float bv[4] = {bt.x, bt.y, bt.z, bt.w};
    float ov[4];
    #pragma unroll
    for (int j = 0; j < 4; j++) {
        float mean = g_sum[c + j] * inv_n;
        float var  = g_sumsq[c + j] * inv_n - mean * mean;
        float inv_std = rsqrtf(var + 1e-5f);
        float mn = (mv[j] - mean) * inv_std * gv[j] + bv[j];
        float t = xv[j] + mn;
        ov[j] = fmaxf(t, 0.0f) + log1pf(expf(-fabsf(t)));
    }
    ((float4*)out)[i] = make_float4(ov[0], ov[1], ov[2], ov[3]);
}

extern "C" void kernel_launch(void* const* d_in, const int* in_sizes, int n_in,
                              void* d_out, int out_size)
{
    const float* x     = (const float*)d_in[0];
    const float* ea    = (const float*)d_in[1];
    const float* Wf    = (const float*)d_in[2];
    const float* bf    = (const float*)d_in[3];
    const float* Ws    = (const float*)d_in[4];
    const float* bs    = (const float*)d_in[5];
    const float* gamma = (const float*)d_in[6];
    const float* beta  = (const float*)d_in[7];
    const int*   esrc  = (const int*)d_in[8];
    const int*   etgt  = (const int*)d_in[9];
    float* out = (float*)d_out;

    int n_nodes = in_sizes[0] / DCH;
    int n_edges = in_sizes[8];
    int total   = n_nodes * DCH;
    int total4  = total / 4;
    int etiles  = (n_edges + TILE_E - 1) / TILE_E;
    int ntiles  = (n_nodes + 127) / 128;

    static bool attr_set = false;
    if (!attr_set) {
        cudaFuncSetAttribute(edge_mma_kernel, cudaFuncAttributeMaxDynamicSharedMemorySize, EDGE_SMEM_BYTES);
        cudaFuncSetAttribute(node_mma_kernel, cudaFuncAttributeMaxDynamicSharedMemorySize, NODE_SMEM_BYTES);
        attr_set = true;
    }

    {   // 1
        int grid = (total4 + 255) / 256;
        if (grid > 1024) grid = 1024;
        zero_kernel<<<grid, 256>>>(total4);
    }
    prep_B_kernel<<<96, 256>>>(Wf, Ws);                                      // 2
    {   // 3
        dim3 grid(148, 2);
        node_mma_kernel<<<grid, 256, NODE_SMEM_BYTES>>>(x, n_nodes, ntiles);
    }
    {   // 4  <- ncu slot
        int grid = 592;
        if (grid > etiles) grid = etiles;
        edge_mma_kernel<<<grid, 128, EDGE_SMEM_BYTES>>>(ea, bf, bs, esrc, etgt, n_edges, etiles);
    }
    stats_kernel<<<512, 256>>>(total4);                                      // 5
    {   // 6
        int grid = (total4 + 255) / 256;
        final_kernel<<<grid, 256>>>(x, gamma, beta, out, total4, 1.0f / (float)n_nodes);
    }
}